// round 13
// baseline (speedup 1.0000x reference)
#include <cuda_runtime.h>
#include <cuda_bf16.h>
#include <cuda_fp16.h>
#include <math.h>
#include <stdint.h>

#define BATCH 8
#define CIN   256
#define CI    128
#define NPOS  4096

// ---------------- scratch (allocation-free: __device__ globals) ----------------
__device__ __align__(16) __nv_bfloat16 g_Xh [(size_t)BATCH * CIN * NPOS];  // x hi [b][c][n]
__device__ __align__(16) __nv_bfloat16 g_Xl [(size_t)BATCH * CIN * NPOS];
__device__ __align__(16) __nv_bfloat16 g_THh[(size_t)BATCH * NPOS * CI];   // theta [b][n][c]
__device__ __align__(16) __nv_bfloat16 g_THl[(size_t)BATCH * NPOS * CI];
__device__ __align__(16) __nv_bfloat16 g_PHh[(size_t)BATCH * NPOS * CI];   // phi   [b][n][c]
__device__ __align__(16) __nv_bfloat16 g_PHl[(size_t)BATCH * NPOS * CI];
__device__ __align__(16) __half        g_G  [(size_t)BATCH * CI * NPOS];   // g fp16 [b][c][n]
__device__ __align__(16) __nv_bfloat16 g_WQh[2 * CI * CIN];   // [theta_w ; phi_w]
__device__ __align__(16) __nv_bfloat16 g_WQl[2 * CI * CIN];
__device__ __align__(16) __nv_bfloat16 g_WGh[CI * CIN];       // g_w [128][256]
__device__ __align__(16) __nv_bfloat16 g_WGl[CI * CIN];
__device__ __align__(16) __half        g_Whalf[CIN * CI];     // W_w fp16 [256][128]
__device__ float g_WY[(size_t)BATCH * CIN * NPOS];            // W(y) [b][o][n]
__device__ float g_psum[256 * CIN];                           // per-CTA BN partials
__device__ float g_psq [256 * CIN];
__device__ float g_mean[CIN];
__device__ float g_rstd[CIN];

// ---------------- helpers ----------------
__device__ __forceinline__ uint32_t s2u(const void* p) {
    uint32_t a;
    asm("{ .reg .u64 t; cvta.to.shared.u64 t, %1; cvt.u32.u64 %0, t; }" : "=r"(a) : "l"(p));
    return a;
}
__device__ __forceinline__ void ldsm4(uint32_t r[4], uint32_t addr) {
    asm volatile("ldmatrix.sync.aligned.m8n8.x4.shared.b16 {%0,%1,%2,%3}, [%4];"
                 : "=r"(r[0]), "=r"(r[1]), "=r"(r[2]), "=r"(r[3]) : "r"(addr));
}
__device__ __forceinline__ void ldsm4t(uint32_t r[4], uint32_t addr) {
    asm volatile("ldmatrix.sync.aligned.m8n8.x4.trans.shared.b16 {%0,%1,%2,%3}, [%4];"
                 : "=r"(r[0]), "=r"(r[1]), "=r"(r[2]), "=r"(r[3]) : "r"(addr));
}
__device__ __forceinline__ void mma16816(float d[4], const uint32_t a[4],
                                         uint32_t b0, uint32_t b1) {
    asm volatile(
        "mma.sync.aligned.m16n8k16.row.col.f32.bf16.bf16.f32 "
        "{%0,%1,%2,%3}, {%4,%5,%6,%7}, {%8,%9}, {%0,%1,%2,%3};"
        : "+f"(d[0]), "+f"(d[1]), "+f"(d[2]), "+f"(d[3])
        : "r"(a[0]), "r"(a[1]), "r"(a[2]), "r"(a[3]), "r"(b0), "r"(b1));
}
__device__ __forceinline__ void mma16816h(float d[4], const uint32_t a[4],
                                          uint32_t b0, uint32_t b1) {
    asm volatile(
        "mma.sync.aligned.m16n8k16.row.col.f32.f16.f16.f32 "
        "{%0,%1,%2,%3}, {%4,%5,%6,%7}, {%8,%9}, {%0,%1,%2,%3};"
        : "+f"(d[0]), "+f"(d[1]), "+f"(d[2]), "+f"(d[3])
        : "r"(a[0]), "r"(a[1]), "r"(a[2]), "r"(a[3]), "r"(b0), "r"(b1));
}
__device__ __forceinline__ void cpa16(uint32_t dst, const void* src) {
    asm volatile("cp.async.cg.shared.global [%0], [%1], 16;" :: "r"(dst), "l"(src));
}
#define CP_COMMIT() asm volatile("cp.async.commit_group;" ::: "memory")
#define CP_WAIT0()  asm volatile("cp.async.wait_group 0;" ::: "memory")
#define CP_WAIT1()  asm volatile("cp.async.wait_group 1;" ::: "memory")

__device__ __forceinline__ uint32_t pkbf(float a, float b, float* ra, float* rb) {
    __nv_bfloat162 h2 = __floats2bfloat162_rn(a, b);
    uint32_t u = *reinterpret_cast<uint32_t*>(&h2);
    *ra = a - __uint_as_float(u << 16);
    *rb = b - __uint_as_float(u & 0xffff0000u);
    return u;
}
__device__ __forceinline__ uint32_t pkbf2(float a, float b) {
    __nv_bfloat162 h2 = __floats2bfloat162_rn(a, b);
    return *reinterpret_cast<uint32_t*>(&h2);
}
__device__ __forceinline__ uint32_t pkh2(float a, float b) {
    __half2 h2 = __floats2half2_rn(a, b);
    return *reinterpret_cast<uint32_t*>(&h2);
}

// =================================================================
// K0: split x -> bf16 hi/lo AND weights (merged; one launch)
// blocks [0,8192): x path.  blocks [8192,8704): weights path.
// =================================================================
__global__ __launch_bounds__(256) void split_all_kernel(
    const float* __restrict__ x,
    const float* __restrict__ thw, const float* __restrict__ phw,
    const float* __restrict__ gw,  const float* __restrict__ Ww)
{
    int bid = blockIdx.x;
    if (bid < 8192) {
        size_t i = ((size_t)bid * 256 + threadIdx.x) * 4;
        float4 v = *(const float4*)&x[i];
        float r0, r1, r2, r3;
        uint32_t h01 = pkbf(v.x, v.y, &r0, &r1);
        uint32_t h23 = pkbf(v.z, v.w, &r2, &r3);
        *(uint2*)&g_Xh[i] = make_uint2(h01, h23);
        *(uint2*)&g_Xl[i] = make_uint2(pkbf2(r0, r1), pkbf2(r2, r3));
        return;
    }
    int i = (bid - 8192) * 256 + threadIdx.x;   // 0..131071
    int which = i >> 15, j = i & 32767;
    if (which == 3) { g_Whalf[j] = __float2half(Ww[j]); return; }
    float v;
    __nv_bfloat16 *dh, *dl;
    int o;
    if (which == 0)      { v = thw[j]; dh = g_WQh; dl = g_WQl; o = j; }
    else if (which == 1) { v = phw[j]; dh = g_WQh; dl = g_WQl; o = 32768 + j; }
    else                 { v = gw[j];  dh = g_WGh; dl = g_WGl; o = j; }
    __nv_bfloat16 h = __float2bfloat16(v);
    dh[o] = h;
    dl[o] = __float2bfloat16(v - __bfloat162float(h));
}

// =================================================================
// K1a: theta/phi projection (HMMA bf16 split) -> [b][n][c] hi/lo.
// z-split: blockIdx.z = 0 theta, 1 phi. 128n x 128o per CTA, occ 2.
// =================================================================
#define PSQ 272
#define PSW 80
#define PN_XH 0
#define PN_XL 8704
#define PN_WH 17408
#define PN_WL 27648
#define PN_BUF 37888
#define PN_BIAS 75776
#define PN_SMEM 76800

__global__ __launch_bounds__(256, 2) void proj_npos_kernel(
    const float* __restrict__ th_b, const float* __restrict__ ph_b)
{
    extern __shared__ __align__(16) char smem[];
    const uint32_t sb = s2u(smem);
    const int t = threadIdx.x, w = t >> 5, L = t & 31;
    const int g = L >> 2, tc = L & 3;
    const int b = blockIdx.y;
    const int n0 = blockIdx.x * 128;
    const int z = blockIdx.z;

    float* bias = (float*)(smem + PN_BIAS);
    if (t < 128) bias[t] = z ? ph_b[t] : th_b[t];

    const __nv_bfloat16* xh = g_Xh + (size_t)b * CIN * NPOS + n0;
    const __nv_bfloat16* xl = g_Xl + (size_t)b * CIN * NPOS + n0;
    const __nv_bfloat16* wh = g_WQh + (size_t)z * 32768;
    const __nv_bfloat16* wl = g_WQl + (size_t)z * 32768;

    const uint32_t aoff = (uint32_t)(((L & 7) + ((L >> 4) & 1) * 8) * PSQ + 32 * w +
                                     ((L >> 3) & 1) * 16);
    const uint32_t boff = (uint32_t)(((L >> 4) * 8 + (L & 7)) * PSW + ((L >> 3) & 1) * 16);

    float acc[16][4];
    #pragma unroll
    for (int j = 0; j < 16; j++)
        #pragma unroll
        for (int k = 0; k < 4; k++) acc[j][k] = 0.f;

    {
        uint32_t base = sb;
        for (int i = t; i < 512; i += 256) {
            int r = i >> 4, c16 = i & 15;
            uint32_t doff = (uint32_t)(r * PSQ + c16 * 16);
            cpa16(base + PN_XH + doff, xh + (size_t)r * NPOS + c16 * 8);
            cpa16(base + PN_XL + doff, xl + (size_t)r * NPOS + c16 * 8);
        }
        for (int i = t; i < 512; i += 256) {
            int r = i >> 2, c4 = i & 3;
            uint32_t doff = (uint32_t)(r * PSW + c4 * 16);
            cpa16(base + PN_WH + doff, wh + (size_t)r * CIN + c4 * 8);
            cpa16(base + PN_WL + doff, wl + (size_t)r * CIN + c4 * 8);
        }
        CP_COMMIT();
    }

    #pragma unroll 1
    for (int ch = 0; ch < 8; ch++) {
        if (ch < 7) {
            int c0 = (ch + 1) * 32;
            uint32_t base = sb + ((ch + 1) & 1) * PN_BUF;
            for (int i = t; i < 512; i += 256) {
                int r = i >> 4, c16 = i & 15;
                uint32_t doff = (uint32_t)(r * PSQ + c16 * 16);
                cpa16(base + PN_XH + doff, xh + (size_t)(c0 + r) * NPOS + c16 * 8);
                cpa16(base + PN_XL + doff, xl + (size_t)(c0 + r) * NPOS + c16 * 8);
            }
            for (int i = t; i < 512; i += 256) {
                int r = i >> 2, c4 = i & 3;
                uint32_t doff = (uint32_t)(r * PSW + c4 * 16);
                cpa16(base + PN_WH + doff, wh + (size_t)r * CIN + c0 + c4 * 8);
                cpa16(base + PN_WL + doff, wl + (size_t)r * CIN + c0 + c4 * 8);
            }
            CP_COMMIT();
            CP_WAIT1();
        } else {
            CP_WAIT0();
        }
        __syncthreads();
        const uint32_t xbase = sb + (ch & 1) * PN_BUF;
        const uint32_t aB = xbase + PN_XH + aoff;
        const uint32_t bB = xbase + PN_WH + boff;
        #pragma unroll
        for (int kk = 0; kk < 2; kk++) {
            uint32_t ah[4], al[4];
            ldsm4t(ah, aB + kk * 16 * PSQ);
            ldsm4t(al, aB + 8704 + kk * 16 * PSQ);
            #pragma unroll
            for (int np = 0; np < 8; np++) {
                uint32_t bh[4], bl[4];
                ldsm4(bh, bB + np * (16 * PSW) + kk * 32);
                ldsm4(bl, bB + 10240 + np * (16 * PSW) + kk * 32);
                mma16816(acc[2 * np],     ah, bh[0], bh[1]);
                mma16816(acc[2 * np + 1], ah, bh[2], bh[3]);
                mma16816(acc[2 * np],     ah, bl[0], bl[1]);
                mma16816(acc[2 * np + 1], ah, bl[2], bl[3]);
                mma16816(acc[2 * np],     al, bh[0], bh[1]);
                mma16816(acc[2 * np + 1], al, bh[2], bh[3]);
            }
        }
        __syncthreads();
    }

    const int nrow = n0 + 16 * w + g;
    const size_t rb0 = ((size_t)b * NPOS + nrow) * CI;
    const size_t rb1 = rb0 + (size_t)8 * CI;
    __nv_bfloat16* dh = z ? g_PHh : g_THh;
    __nv_bfloat16* dl = z ? g_PHl : g_THl;
    #pragma unroll
    for (int j = 0; j < 16; j++) {
        int o = 8 * j + 2 * tc;
        float b0 = bias[o], b1 = bias[o + 1];
        float r0, r1;
        uint32_t hp = pkbf(acc[j][0] + b0, acc[j][1] + b1, &r0, &r1);
        uint32_t lp = pkbf2(r0, r1);
        *(uint32_t*)(dh + rb0 + o) = hp;
        *(uint32_t*)(dl + rb0 + o) = lp;
        hp = pkbf(acc[j][2] + b0, acc[j][3] + b1, &r0, &r1);
        lp = pkbf2(r0, r1);
        *(uint32_t*)(dh + rb1 + o) = hp;
        *(uint32_t*)(dl + rb1 + o) = lp;
    }
}

// =================================================================
// K1b: g projection (HMMA bf16 split) -> fp16 single [b][c][n], occ 2
// =================================================================
#define PG_XH 0
#define PG_XL 8704
#define PG_WH 17408
#define PG_WL 27648
#define PG_BUF 37888
#define PG_BIAS 75776
#define PG_SMEM 76800

__global__ __launch_bounds__(256, 2) void proj_chan_kernel(const float* __restrict__ g_b)
{
    extern __shared__ __align__(16) char smem[];
    const uint32_t sb = s2u(smem);
    const int t = threadIdx.x, w = t >> 5, L = t & 31;
    const int g = L >> 2, tc = L & 3;
    const int b = blockIdx.y;
    const int n0 = blockIdx.x * 128;

    float* bias = (float*)(smem + PG_BIAS);
    if (t < 128) bias[t] = g_b[t];

    const __nv_bfloat16* xh = g_Xh + (size_t)b * CIN * NPOS + n0;
    const __nv_bfloat16* xl = g_Xl + (size_t)b * CIN * NPOS + n0;

    const uint32_t aoff = (uint32_t)((16 * w + (L & 7) + ((L >> 3) & 1) * 8) * PSW +
                                     (L >> 4) * 16);
    const uint32_t boff = (uint32_t)(((L & 7) + ((L >> 3) & 1) * 8) * PSQ + (L >> 4) * 16);

    float acc[16][4];
    #pragma unroll
    for (int j = 0; j < 16; j++)
        #pragma unroll
        for (int k = 0; k < 4; k++) acc[j][k] = 0.f;

    {
        uint32_t base = sb;
        for (int i = t; i < 512; i += 256) {
            int r = i >> 4, c16 = i & 15;
            uint32_t doff = (uint32_t)(r * PSQ + c16 * 16);
            cpa16(base + PG_XH + doff, xh + (size_t)r * NPOS + c16 * 8);
            cpa16(base + PG_XL + doff, xl + (size_t)r * NPOS + c16 * 8);
        }
        for (int i = t; i < 512; i += 256) {
            int r = i >> 2, c4 = i & 3;
            uint32_t doff = (uint32_t)(r * PSW + c4 * 16);
            cpa16(base + PG_WH + doff, g_WGh + (size_t)r * CIN + c4 * 8);
            cpa16(base + PG_WL + doff, g_WGl + (size_t)r * CIN + c4 * 8);
        }
        CP_COMMIT();
    }

    #pragma unroll 1
    for (int ch = 0; ch < 8; ch++) {
        if (ch < 7) {
            int c0 = (ch + 1) * 32;
            uint32_t base = sb + ((ch + 1) & 1) * PG_BUF;
            for (int i = t; i < 512; i += 256) {
                int r = i >> 4, c16 = i & 15;
                uint32_t doff = (uint32_t)(r * PSQ + c16 * 16);
                cpa16(base + PG_XH + doff, xh + (size_t)(c0 + r) * NPOS + c16 * 8);
                cpa16(base + PG_XL + doff, xl + (size_t)(c0 + r) * NPOS + c16 * 8);
            }
            for (int i = t; i < 512; i += 256) {
                int r = i >> 2, c4 = i & 3;
                uint32_t doff = (uint32_t)(r * PSW + c4 * 16);
                cpa16(base + PG_WH + doff, g_WGh + (size_t)r * CIN + c0 + c4 * 8);
                cpa16(base + PG_WL + doff, g_WGl + (size_t)r * CIN + c0 + c4 * 8);
            }
            CP_COMMIT();
            CP_WAIT1();
        } else {
            CP_WAIT0();
        }
        __syncthreads();
        const uint32_t xbase = sb + (ch & 1) * PG_BUF;
        const uint32_t aB = xbase + PG_WH + aoff;
        const uint32_t bB = xbase + PG_XH + boff;
        #pragma unroll
        for (int kk = 0; kk < 2; kk++) {
            uint32_t ah[4], al[4];
            ldsm4(ah, aB + kk * 32);
            ldsm4(al, aB + 10240 + kk * 32);
            #pragma unroll
            for (int np = 0; np < 8; np++) {
                uint32_t bh[4], bl[4];
                ldsm4t(bh, bB + np * 32 + kk * 16 * PSQ);
                ldsm4t(bl, bB + 8704 + np * 32 + kk * 16 * PSQ);
                mma16816(acc[2 * np],     ah, bh[0], bh[1]);
                mma16816(acc[2 * np + 1], ah, bh[2], bh[3]);
                mma16816(acc[2 * np],     ah, bl[0], bl[1]);
                mma16816(acc[2 * np + 1], ah, bl[2], bl[3]);
                mma16816(acc[2 * np],     al, bh[0], bh[1]);
                mma16816(acc[2 * np + 1], al, bh[2], bh[3]);
            }
        }
        __syncthreads();
    }

    const int o = 16 * w + g;
    const float b0 = bias[o], b8 = bias[o + 8];
    #pragma unroll
    for (int j = 0; j < 16; j++) {
        int n = 16 * (j >> 1) + 8 * (j & 1) + 2 * tc;
        size_t a0 = ((size_t)b * CI + o) * NPOS + n0 + n;
        size_t a8 = a0 + (size_t)8 * NPOS;
        *(uint32_t*)(g_G + a0) = pkh2(acc[j][0] + b0, acc[j][1] + b0);
        *(uint32_t*)(g_G + a8) = pkh2(acc[j][2] + b8, acc[j][3] + b8);
    }
}

// =================================================================
// K2: attention — QK bf16 3-term (Q resident), PV fp16 (flash online max),
// W-conv fp16 full-W staging, fused deterministic BN partials.
// =================================================================
#define SQ  272
#define SPG 144
#define SM_QH  0
#define SM_QL  34816
#define SM_K0  69632
#define SM_K1  104448
#define SM_G0  139264
#define SM_G1  157696
#define SMEM_BYTES 176128
#define SM_WB  69632            // epilogue: full 256-row W tile aliases K0+K1
#define SM_PS  139264           // epilogue: BN partial smem aliases G0 (8KB)

__global__ __launch_bounds__(256, 1) void attn_mma_kernel(const float* __restrict__ W_b)
{
    extern __shared__ __align__(16) char smem[];
    const uint32_t sb = s2u(smem);
    const int t = threadIdx.x, w = t >> 5, L = t & 31;
    const int b = blockIdx.y;
    const int q0 = blockIdx.x * 128;
    const int g  = L >> 2, tc = L & 3;

    const __nv_bfloat16* qh  = g_THh + ((size_t)b * NPOS + q0) * CI;
    const __nv_bfloat16* ql  = g_THl + ((size_t)b * NPOS + q0) * CI;
    const __nv_bfloat16* khb = g_PHh + (size_t)b * NPOS * CI;
    const __nv_bfloat16* klb = g_PHl + (size_t)b * NPOS * CI;
    const __half*        ghb = g_G + (size_t)b * CI * NPOS;

    for (int i = t; i < 2048; i += 256) {
        int r = i >> 4, c16 = i & 15;
        uint32_t doff = (uint32_t)(r * SQ + c16 * 16);
        cpa16(sb + SM_QH + doff, qh + (size_t)r * CI + c16 * 8);
        cpa16(sb + SM_QL + doff, ql + (size_t)r * CI + c16 * 8);
    }
    for (int i = t; i < 1024; i += 256) {
        int r = i >> 4, c16 = i & 15;
        uint32_t doff = (uint32_t)(r * SQ + c16 * 16);
        cpa16(sb + SM_K0 + doff, khb + (size_t)r * CI + c16 * 8);
        cpa16(sb + SM_K0 + 17408 + doff, klb + (size_t)r * CI + c16 * 8);
    }
    for (int i = t; i < 1024; i += 256) {
        int r = i >> 3, c8 = i & 7;
        cpa16(sb + SM_G0 + (uint32_t)(r * SPG + c8 * 16), ghb + (size_t)r * NPOS + c8 * 8);
    }
    CP_COMMIT();

    const int lr = ((L >> 3) & 1) * 8 + (L & 7);
    const int lk = (L >> 4) * 16;
    const int bn = (L >> 4) * 8 + (L & 7);
    const int bk = ((L >> 3) & 1) * 16;

    const uint32_t aQh = sb + SM_QH + (uint32_t)((16 * w + lr) * SQ + lk);
    const uint32_t aQl = aQh + (SM_QL - SM_QH);
    const uint32_t kOff = (uint32_t)(bn * SQ + bk);
    const uint32_t gOff = (uint32_t)(bn * SPG + bk);

    CP_WAIT0();
    __syncthreads();
    uint32_t qfh[8][4], qfl[8][4];
    #pragma unroll
    for (int kk = 0; kk < 8; kk++) {
        ldsm4(qfh[kk], aQh + kk * 32);
        ldsm4(qfl[kk], aQl + kk * 32);
    }

    float yacc[16][4];
    #pragma unroll
    for (int n = 0; n < 16; n++)
        #pragma unroll
        for (int j = 0; j < 4; j++) yacc[n][j] = 0.f;
    float ls0 = 0.f, ls1 = 0.f;
    float m0 = -INFINITY, m1 = -INFINITY;

    #pragma unroll 1
    for (int mt = 0; mt < NPOS / 64; mt++) {
        if (mt > 0) {
            CP_WAIT0();
            __syncthreads();
        }

        if (mt < 63) {
            const int m1i = mt * 64 + 64;
            const uint32_t kdst = sb + (((mt + 1) & 1) ? SM_K1 : SM_K0);
            const uint32_t gdst = sb + (((mt + 1) & 1) ? SM_G1 : SM_G0);
            for (int i = t; i < 1024; i += 256) {
                int r = i >> 4, c16 = i & 15;
                uint32_t doff = (uint32_t)(r * SQ + c16 * 16);
                cpa16(kdst + doff, khb + (size_t)(m1i + r) * CI + c16 * 8);
                cpa16(kdst + 17408 + doff, klb + (size_t)(m1i + r) * CI + c16 * 8);
            }
            for (int i = t; i < 1024; i += 256) {
                int r = i >> 3, c8 = i & 7;
                cpa16(gdst + (uint32_t)(r * SPG + c8 * 16),
                      ghb + (size_t)r * NPOS + m1i + c8 * 8);
            }
            CP_COMMIT();
        }

        // ---- QK: bf16 3-term ----
        const uint32_t bKh = sb + ((mt & 1) ? SM_K1 : SM_K0) + kOff;
        const uint32_t bKl = bKh + 17408;
        float acc[8][4];
        #pragma unroll
        for (int n = 0; n < 8; n++)
            #pragma unroll
            for (int j = 0; j < 4; j++) acc[n][j] = 0.f;
        #pragma unroll
        for (int kk = 0; kk < 8; kk++) {
            #pragma unroll
            for (int np = 0; np < 4; np++) {
                uint32_t bh[4], bl[4];
                ldsm4(bh, bKh + np * (16 * SQ) + kk * 32);
                ldsm4(bl, bKl + np * (16 * SQ) + kk * 32);
                mma16816(acc[2 * np],     qfh[kk], bh[0], bh[1]);
                mma16816(acc[2 * np + 1], qfh[kk], bh[2], bh[3]);
                mma16816(acc[2 * np],     qfh[kk], bl[0], bl[1]);
                mma16816(acc[2 * np + 1], qfh[kk], bl[2], bl[3]);
                mma16816(acc[2 * np],     qfl[kk], bh[0], bh[1]);
                mma16816(acc[2 * np + 1], qfl[kk], bh[2], bh[3]);
            }
        }

        // ---- flash online-max softmax (skip-rescale vote) ----
        float tm0 = -INFINITY, tm1 = -INFINITY;
        #pragma unroll
        for (int n = 0; n < 8; n++) {
            tm0 = fmaxf(tm0, fmaxf(acc[n][0], acc[n][1]));
            tm1 = fmaxf(tm1, fmaxf(acc[n][2], acc[n][3]));
        }
        tm0 = fmaxf(tm0, __shfl_xor_sync(0xffffffffu, tm0, 1));
        tm0 = fmaxf(tm0, __shfl_xor_sync(0xffffffffu, tm0, 2));
        tm1 = fmaxf(tm1, __shfl_xor_sync(0xffffffffu, tm1, 1));
        tm1 = fmaxf(tm1, __shfl_xor_sync(0xffffffffu, tm1, 2));
        bool noup = (tm0 <= m0) && (tm1 <= m1);
        if (!__all_sync(0xffffffffu, noup)) {
            float mn0 = fmaxf(m0, tm0), mn1 = fmaxf(m1, tm1);
            float al0 = __expf(m0 - mn0), al1 = __expf(m1 - mn1);
            m0 = mn0; m1 = mn1;
            ls0 *= al0; ls1 *= al1;
            #pragma unroll
            for (int n = 0; n < 16; n++) {
                yacc[n][0] *= al0; yacc[n][1] *= al0;
                yacc[n][2] *= al1; yacc[n][3] *= al1;
            }
        }

        uint32_t pf[4][4];
        #pragma unroll
        for (int n = 0; n < 8; n++) {
            float p0 = __expf(acc[n][0] - m0);
            float p1 = __expf(acc[n][1] - m0);
            float p2 = __expf(acc[n][2] - m1);
            float p3 = __expf(acc[n][3] - m1);
            ls0 += p0 + p1;
            ls1 += p2 + p3;
            int kk = n >> 1, e = (n & 1) * 2;
            pf[kk][e]     = pkh2(p0, p1);
            pf[kk][e + 1] = pkh2(p2, p3);
        }

        // ---- PV (fp16 single term) ----
        const uint32_t bG = sb + ((mt & 1) ? SM_G1 : SM_G0) + gOff;
        #pragma unroll
        for (int kk = 0; kk < 4; kk++) {
            #pragma unroll
            for (int np = 0; np < 8; np++) {
                uint32_t bh[4];
                ldsm4(bh, bG + np * (16 * SPG) + kk * 32);
                mma16816h(yacc[2 * np],     pf[kk], bh[0], bh[1]);
                mma16816h(yacc[2 * np + 1], pf[kk], bh[2], bh[3]);
            }
        }
    }

    // ---- finalize row sums ----
    ls0 += __shfl_xor_sync(0xffffffffu, ls0, 1);
    ls0 += __shfl_xor_sync(0xffffffffu, ls0, 2);
    ls1 += __shfl_xor_sync(0xffffffffu, ls1, 1);
    ls1 += __shfl_xor_sync(0xffffffffu, ls1, 2);

    uint32_t yf[8][4];
    {
        float rv0 = 1.f / ls0, rv1 = 1.f / ls1;
        #pragma unroll
        for (int n = 0; n < 16; n++) {
            int kk = n >> 1, e = (n & 1) * 2;
            yf[kk][e]     = pkh2(yacc[n][0] * rv0, yacc[n][1] * rv0);
            yf[kk][e + 1] = pkh2(yacc[n][2] * rv1, yacc[n][3] * rv1);
        }
    }

    // ---- stage FULL 256-row W once (aliases K0+K1) ----
    __syncthreads();
    for (int i = t; i < 4096; i += 256) {
        int r = i >> 4, c16 = i & 15;
        *(uint4*)(smem + SM_WB + (uint32_t)(r * SQ + c16 * 16)) =
            *(const uint4*)(g_Whalf + (size_t)r * CI + c16 * 8);
    }
    __syncthreads();

    const uint32_t bW = sb + SM_WB + (uint32_t)(bn * SQ + bk);
    float* WYb = g_WY + (size_t)b * CIN * NPOS + q0;
    float* psum_s = (float*)(smem + SM_PS);           // [8 warps][128 ch]
    float* psq_s  = (float*)(smem + SM_PS + 4096);
    const int ctaid = b * 32 + blockIdx.x;

    #pragma unroll 1
    for (int h = 0; h < 2; h++) {
        const uint32_t bWh_ = bW + (uint32_t)(h * 128 * SQ);
        float wacc[16][4];
        #pragma unroll
        for (int n = 0; n < 16; n++)
            #pragma unroll
            for (int j = 0; j < 4; j++) wacc[n][j] = 0.f;

        #pragma unroll
        for (int kk = 0; kk < 8; kk++) {
            #pragma unroll
            for (int np = 0; np < 8; np++) {
                uint32_t bh[4];
                ldsm4(bh, bWh_ + np * (16 * SQ) + kk * 32);
                mma16816h(wacc[2 * np],     yf[kk], bh[0], bh[1]);
                mma16816h(wacc[2 * np + 1], yf[kk], bh[2], bh[3]);
            }
        }

        #pragma unroll
        for (int n = 0; n < 16; n++) {
            int o = h * 128 + 8 * n + 2 * tc;
            float b0 = __ldg(&W_b[o]);
            float b1 = __ldg(&W_b[o + 1]);
            int r0 = 16 * w + g;
            float v0 = wacc[n][0] + b0, v1 = wacc[n][1] + b1;
            float v2 = wacc[n][2] + b0, v3 = wacc[n][3] + b1;
            WYb[(size_t)o * NPOS + r0]           = v0;
            WYb[(size_t)(o + 1) * NPOS + r0]     = v1;
            WYb[(size_t)o * NPOS + r0 + 8]       = v2;
            WYb[(size_t)(o + 1) * NPOS + r0 + 8] = v3;
            // BN partials: sum over this warp's 16 positions (reduce over g)
            float p0 = v0 + v2, p1 = v1 + v3;
            float q0s = v0 * v0 + v2 * v2, q1s = v1 * v1 + v3 * v3;
            #pragma unroll
            for (int off = 4; off <= 16; off <<= 1) {
                p0  += __shfl_xor_sync(0xffffffffu, p0, off);
                p1  += __shfl_xor_sync(0xffffffffu, p1, off);
                q0s += __shfl_xor_sync(0xffffffffu, q0s, off);
                q1s += __shfl_xor_sync(0xffffffffu, q1s, off);
            }
            if (g == 0) {
                int c = 8 * n + 2 * tc;
                psum_s[w * 128 + c]     = p0;
                psum_s[w * 128 + c + 1] = p1;
                psq_s [w * 128 + c]     = q0s;
                psq_s [w * 128 + c + 1] = q1s;
            }
        }
        __syncthreads();
        if (t < 128) {
            float s = 0.f, ss = 0.f;
            #pragma unroll
            for (int wi = 0; wi < 8; wi++) {
                s  += psum_s[wi * 128 + t];
                ss += psq_s [wi * 128 + t];
            }
            g_psum[(size_t)ctaid * CIN + h * 128 + t] = s;
            g_psq [(size_t)ctaid * CIN + h * 128 + t] = ss;
        }
        __syncthreads();
    }
}

// =================================================================
// K3: BN finalize — reduce 256 deterministic per-CTA partials
// =================================================================
__global__ __launch_bounds__(256) void stats_fin_kernel()
{
    const int c = threadIdx.x;
    float s = 0.f, ss = 0.f;
    for (int i = 0; i < 256; i++) {
        s  += g_psum[(size_t)i * CIN + c];
        ss += g_psq [(size_t)i * CIN + c];
    }
    const float inv = 1.f / (float)(BATCH * NPOS);
    float mean = s * inv;
    float var  = ss * inv - mean * mean;
    g_mean[c] = mean;
    g_rstd[c] = rsqrtf(var + 1e-5f);
}

// =================================================================
// K4: z = (wy - mean)*rstd*gamma + beta + x
// =================================================================
__global__ __launch_bounds__(256) void final_kernel(
    const float* __restrict__ x,
    const float* __restrict__ gamma, const float* __restrict__ beta,
    float* __restrict__ z)
{
    size_t i4 = (size_t)blockIdx.x * 256 + threadIdx.x;
    size_t i  = i4 * 4;
    int c = (int)((i >> 12) & 255);
    float m = g_mean[c], r = g_rstd[c], ga = gamma[c], be = beta[c];
    float4 wy = *(const float4*)&g_WY[i];
    float4 xv = *(const float4*)&x[i];
    float4 o;
    o.x = (wy.x - m) * r * ga + be + xv.x;
    o.y = (wy.y - m) * r * ga + be + xv.y;
    o.z = (wy.z - m) * r * ga + be + xv.z;
    o.w = (wy.w - m) * r * ga + be + xv.w;
    *(float4*)&z[i] = o;
}

// =================================================================
extern "C" void kernel_launch(void* const* d_in, const int* in_sizes, int n_in,
                              void* d_out, int out_size)
{
    const float* x       = (const float*)d_in[0];
    const float* g_w     = (const float*)d_in[1];
    const float* g_b     = (const float*)d_in[2];
    const float* theta_w = (const float*)d_in[3];
    const float* theta_b = (const float*)d_in[4];
    const float* phi_w   = (const float*)d_in[5];
    const float* phi_b   = (const float*)d_in[6];
    const float* W_w     = (const float*)d_in[7];
    const float* W_b     = (const float*)d_in[8];
    const float* bn_g    = (const float*)d_in[9];
    const float* bn_b    = (const float*)d_in[10];
    float* z = (float*)d_out;

    cudaFuncSetAttribute(proj_npos_kernel, cudaFuncAttributeMaxDynamicSharedMemorySize, PN_SMEM);
    cudaFuncSetAttribute(proj_chan_kernel, cudaFuncAttributeMaxDynamicSharedMemorySize, PG_SMEM);
    cudaFuncSetAttribute(attn_mma_kernel,  cudaFuncAttributeMaxDynamicSharedMemorySize, SMEM_BYTES);

    split_all_kernel<<<8704, 256>>>(x, theta_w, phi_w, g_w, W_w);
    proj_npos_kernel<<<dim3(32, 8, 2), 256, PN_SMEM>>>(theta_b, phi_b);
    proj_chan_kernel<<<dim3(32, 8), 256, PG_SMEM>>>(g_b);
    attn_mma_kernel<<<dim3(32, 8), 256, SMEM_BYTES>>>(W_b);
    stats_fin_kernel<<<1, 256>>>();
    final_kernel<<<8192, 256>>>(x, bn_g, bn_b, z);
}

// round 14
// speedup vs baseline: 1.0088x; 1.0088x over previous
#include <cuda_runtime.h>
#include <cuda_bf16.h>
#include <cuda_fp16.h>
#include <math.h>
#include <stdint.h>

#define BATCH 8
#define CIN   256
#define CI    128
#define NPOS  4096

// ---------------- scratch (allocation-free: __device__ globals) ----------------
__device__ __align__(16) __nv_bfloat16 g_Xh [(size_t)BATCH * CIN * NPOS];
__device__ __align__(16) __nv_bfloat16 g_Xl [(size_t)BATCH * CIN * NPOS];
__device__ __align__(16) __nv_bfloat16 g_THh[(size_t)BATCH * NPOS * CI];
__device__ __align__(16) __nv_bfloat16 g_THl[(size_t)BATCH * NPOS * CI];
__device__ __align__(16) __nv_bfloat16 g_PHh[(size_t)BATCH * NPOS * CI];
__device__ __align__(16) __nv_bfloat16 g_PHl[(size_t)BATCH * NPOS * CI];
__device__ __align__(16) __half        g_G  [(size_t)BATCH * CI * NPOS];
__device__ __align__(16) __nv_bfloat16 g_WQh[2 * CI * CIN];
__device__ __align__(16) __nv_bfloat16 g_WQl[2 * CI * CIN];
__device__ __align__(16) __nv_bfloat16 g_WGh[CI * CIN];
__device__ __align__(16) __nv_bfloat16 g_WGl[CI * CIN];
__device__ __align__(16) __half        g_Whalf[CIN * CI];
__device__ float g_WY[(size_t)BATCH * CIN * NPOS];
__device__ float g_ps[4 * CIN], g_pss[4 * CIN];
__device__ float g_mean[CIN];
__device__ float g_rstd[CIN];

// ---------------- helpers ----------------
__device__ __forceinline__ uint32_t s2u(const void* p) {
    uint32_t a;
    asm("{ .reg .u64 t; cvta.to.shared.u64 t, %1; cvt.u32.u64 %0, t; }" : "=r"(a) : "l"(p));
    return a;
}
__device__ __forceinline__ void ldsm4(uint32_t r[4], uint32_t addr) {
    asm volatile("ldmatrix.sync.aligned.m8n8.x4.shared.b16 {%0,%1,%2,%3}, [%4];"
                 : "=r"(r[0]), "=r"(r[1]), "=r"(r[2]), "=r"(r[3]) : "r"(addr));
}
__device__ __forceinline__ void ldsm4t(uint32_t r[4], uint32_t addr) {
    asm volatile("ldmatrix.sync.aligned.m8n8.x4.trans.shared.b16 {%0,%1,%2,%3}, [%4];"
                 : "=r"(r[0]), "=r"(r[1]), "=r"(r[2]), "=r"(r[3]) : "r"(addr));
}
__device__ __forceinline__ void mma16816(float d[4], const uint32_t a[4],
                                         uint32_t b0, uint32_t b1) {
    asm volatile(
        "mma.sync.aligned.m16n8k16.row.col.f32.bf16.bf16.f32 "
        "{%0,%1,%2,%3}, {%4,%5,%6,%7}, {%8,%9}, {%0,%1,%2,%3};"
        : "+f"(d[0]), "+f"(d[1]), "+f"(d[2]), "+f"(d[3])
        : "r"(a[0]), "r"(a[1]), "r"(a[2]), "r"(a[3]), "r"(b0), "r"(b1));
}
__device__ __forceinline__ void mma16816h(float d[4], const uint32_t a[4],
                                          uint32_t b0, uint32_t b1) {
    asm volatile(
        "mma.sync.aligned.m16n8k16.row.col.f32.f16.f16.f32 "
        "{%0,%1,%2,%3}, {%4,%5,%6,%7}, {%8,%9}, {%0,%1,%2,%3};"
        : "+f"(d[0]), "+f"(d[1]), "+f"(d[2]), "+f"(d[3])
        : "r"(a[0]), "r"(a[1]), "r"(a[2]), "r"(a[3]), "r"(b0), "r"(b1));
}
__device__ __forceinline__ void cpa16(uint32_t dst, const void* src) {
    asm volatile("cp.async.cg.shared.global [%0], [%1], 16;" :: "r"(dst), "l"(src));
}
#define CP_COMMIT() asm volatile("cp.async.commit_group;" ::: "memory")
#define CP_WAIT0()  asm volatile("cp.async.wait_group 0;" ::: "memory")
#define CP_WAIT1()  asm volatile("cp.async.wait_group 1;" ::: "memory")

__device__ __forceinline__ uint32_t pkbf(float a, float b, float* ra, float* rb) {
    __nv_bfloat162 h2 = __floats2bfloat162_rn(a, b);
    uint32_t u = *reinterpret_cast<uint32_t*>(&h2);
    *ra = a - __uint_as_float(u << 16);
    *rb = b - __uint_as_float(u & 0xffff0000u);
    return u;
}
__device__ __forceinline__ uint32_t pkbf2(float a, float b) {
    __nv_bfloat162 h2 = __floats2bfloat162_rn(a, b);
    return *reinterpret_cast<uint32_t*>(&h2);
}
__device__ __forceinline__ uint32_t pkh2(float a, float b) {
    __half2 h2 = __floats2half2_rn(a, b);
    return *reinterpret_cast<uint32_t*>(&h2);
}

// =================================================================
// K0: split x (bf16 hi/lo) + all weights, one launch
// =================================================================
__global__ __launch_bounds__(256) void split_all_kernel(
    const float* __restrict__ x,
    const float* __restrict__ thw, const float* __restrict__ phw,
    const float* __restrict__ gw,  const float* __restrict__ Ww)
{
    int bid = blockIdx.x;
    if (bid < 8192) {
        size_t i = ((size_t)bid * 256 + threadIdx.x) * 4;
        float4 v = *(const float4*)&x[i];
        float r0, r1, r2, r3;
        uint32_t h01 = pkbf(v.x, v.y, &r0, &r1);
        uint32_t h23 = pkbf(v.z, v.w, &r2, &r3);
        *(uint2*)&g_Xh[i] = make_uint2(h01, h23);
        *(uint2*)&g_Xl[i] = make_uint2(pkbf2(r0, r1), pkbf2(r2, r3));
        return;
    }
    int i = (bid - 8192) * 256 + threadIdx.x;
    int which = i >> 15, j = i & 32767;
    if (which == 3) { g_Whalf[j] = __float2half(Ww[j]); return; }
    float v;
    __nv_bfloat16 *dh, *dl;
    int o;
    if (which == 0)      { v = thw[j]; dh = g_WQh; dl = g_WQl; o = j; }
    else if (which == 1) { v = phw[j]; dh = g_WQh; dl = g_WQl; o = 32768 + j; }
    else                 { v = gw[j];  dh = g_WGh; dl = g_WGl; o = j; }
    __nv_bfloat16 h = __float2bfloat16(v);
    dh[o] = h;
    dl[o] = __float2bfloat16(v - __bfloat162float(h));
}

// =================================================================
// K1a: theta/phi projection (z-split, occ 2) -> [b][n][c] hi/lo
// =================================================================
#define PSQ 272
#define PSW 80
#define PN_XH 0
#define PN_XL 8704
#define PN_WH 17408
#define PN_WL 27648
#define PN_BUF 37888
#define PN_BIAS 75776
#define PN_SMEM 76800

__global__ __launch_bounds__(256, 2) void proj_npos_kernel(
    const float* __restrict__ th_b, const float* __restrict__ ph_b)
{
    extern __shared__ __align__(16) char smem[];
    const uint32_t sb = s2u(smem);
    const int t = threadIdx.x, w = t >> 5, L = t & 31;
    const int g = L >> 2, tc = L & 3;
    const int b = blockIdx.y;
    const int n0 = blockIdx.x * 128;
    const int z = blockIdx.z;

    float* bias = (float*)(smem + PN_BIAS);
    if (t < 128) bias[t] = z ? ph_b[t] : th_b[t];

    const __nv_bfloat16* xh = g_Xh + (size_t)b * CIN * NPOS + n0;
    const __nv_bfloat16* xl = g_Xl + (size_t)b * CIN * NPOS + n0;
    const __nv_bfloat16* wh = g_WQh + (size_t)z * 32768;
    const __nv_bfloat16* wl = g_WQl + (size_t)z * 32768;

    const uint32_t aoff = (uint32_t)(((L & 7) + ((L >> 4) & 1) * 8) * PSQ + 32 * w +
                                     ((L >> 3) & 1) * 16);
    const uint32_t boff = (uint32_t)(((L >> 4) * 8 + (L & 7)) * PSW + ((L >> 3) & 1) * 16);

    float acc[16][4];
    #pragma unroll
    for (int j = 0; j < 16; j++)
        #pragma unroll
        for (int k = 0; k < 4; k++) acc[j][k] = 0.f;

    {
        uint32_t base = sb;
        for (int i = t; i < 512; i += 256) {
            int r = i >> 4, c16 = i & 15;
            uint32_t doff = (uint32_t)(r * PSQ + c16 * 16);
            cpa16(base + PN_XH + doff, xh + (size_t)r * NPOS + c16 * 8);
            cpa16(base + PN_XL + doff, xl + (size_t)r * NPOS + c16 * 8);
        }
        for (int i = t; i < 512; i += 256) {
            int r = i >> 2, c4 = i & 3;
            uint32_t doff = (uint32_t)(r * PSW + c4 * 16);
            cpa16(base + PN_WH + doff, wh + (size_t)r * CIN + c4 * 8);
            cpa16(base + PN_WL + doff, wl + (size_t)r * CIN + c4 * 8);
        }
        CP_COMMIT();
    }

    #pragma unroll 1
    for (int ch = 0; ch < 8; ch++) {
        if (ch < 7) {
            int c0 = (ch + 1) * 32;
            uint32_t base = sb + ((ch + 1) & 1) * PN_BUF;
            for (int i = t; i < 512; i += 256) {
                int r = i >> 4, c16 = i & 15;
                uint32_t doff = (uint32_t)(r * PSQ + c16 * 16);
                cpa16(base + PN_XH + doff, xh + (size_t)(c0 + r) * NPOS + c16 * 8);
                cpa16(base + PN_XL + doff, xl + (size_t)(c0 + r) * NPOS + c16 * 8);
            }
            for (int i = t; i < 512; i += 256) {
                int r = i >> 2, c4 = i & 3;
                uint32_t doff = (uint32_t)(r * PSW + c4 * 16);
                cpa16(base + PN_WH + doff, wh + (size_t)r * CIN + c0 + c4 * 8);
                cpa16(base + PN_WL + doff, wl + (size_t)r * CIN + c0 + c4 * 8);
            }
            CP_COMMIT();
            CP_WAIT1();
        } else {
            CP_WAIT0();
        }
        __syncthreads();
        const uint32_t xbase = sb + (ch & 1) * PN_BUF;
        const uint32_t aB = xbase + PN_XH + aoff;
        const uint32_t bB = xbase + PN_WH + boff;
        #pragma unroll
        for (int kk = 0; kk < 2; kk++) {
            uint32_t ah[4], al[4];
            ldsm4t(ah, aB + kk * 16 * PSQ);
            ldsm4t(al, aB + 8704 + kk * 16 * PSQ);
            #pragma unroll
            for (int np = 0; np < 8; np++) {
                uint32_t bh[4], bl[4];
                ldsm4(bh, bB + np * (16 * PSW) + kk * 32);
                ldsm4(bl, bB + 10240 + np * (16 * PSW) + kk * 32);
                mma16816(acc[2 * np],     ah, bh[0], bh[1]);
                mma16816(acc[2 * np + 1], ah, bh[2], bh[3]);
                mma16816(acc[2 * np],     ah, bl[0], bl[1]);
                mma16816(acc[2 * np + 1], ah, bl[2], bl[3]);
                mma16816(acc[2 * np],     al, bh[0], bh[1]);
                mma16816(acc[2 * np + 1], al, bh[2], bh[3]);
            }
        }
        __syncthreads();
    }

    const int nrow = n0 + 16 * w + g;
    const size_t rb0 = ((size_t)b * NPOS + nrow) * CI;
    const size_t rb1 = rb0 + (size_t)8 * CI;
    __nv_bfloat16* dh = z ? g_PHh : g_THh;
    __nv_bfloat16* dl = z ? g_PHl : g_THl;
    #pragma unroll
    for (int j = 0; j < 16; j++) {
        int o = 8 * j + 2 * tc;
        float b0 = bias[o], b1 = bias[o + 1];
        float r0, r1;
        uint32_t hp = pkbf(acc[j][0] + b0, acc[j][1] + b1, &r0, &r1);
        uint32_t lp = pkbf2(r0, r1);
        *(uint32_t*)(dh + rb0 + o) = hp;
        *(uint32_t*)(dl + rb0 + o) = lp;
        hp = pkbf(acc[j][2] + b0, acc[j][3] + b1, &r0, &r1);
        lp = pkbf2(r0, r1);
        *(uint32_t*)(dh + rb1 + o) = hp;
        *(uint32_t*)(dl + rb1 + o) = lp;
    }
}

// =================================================================
// K1b: g projection -> fp16 single [b][c][n], occ 2
// =================================================================
#define PG_XH 0
#define PG_XL 8704
#define PG_WH 17408
#define PG_WL 27648
#define PG_BUF 37888
#define PG_BIAS 75776
#define PG_SMEM 76800

__global__ __launch_bounds__(256, 2) void proj_chan_kernel(const float* __restrict__ g_b)
{
    extern __shared__ __align__(16) char smem[];
    const uint32_t sb = s2u(smem);
    const int t = threadIdx.x, w = t >> 5, L = t & 31;
    const int g = L >> 2, tc = L & 3;
    const int b = blockIdx.y;
    const int n0 = blockIdx.x * 128;

    float* bias = (float*)(smem + PG_BIAS);
    if (t < 128) bias[t] = g_b[t];

    const __nv_bfloat16* xh = g_Xh + (size_t)b * CIN * NPOS + n0;
    const __nv_bfloat16* xl = g_Xl + (size_t)b * CIN * NPOS + n0;

    const uint32_t aoff = (uint32_t)((16 * w + (L & 7) + ((L >> 3) & 1) * 8) * PSW +
                                     (L >> 4) * 16);
    const uint32_t boff = (uint32_t)(((L & 7) + ((L >> 3) & 1) * 8) * PSQ + (L >> 4) * 16);

    float acc[16][4];
    #pragma unroll
    for (int j = 0; j < 16; j++)
        #pragma unroll
        for (int k = 0; k < 4; k++) acc[j][k] = 0.f;

    {
        uint32_t base = sb;
        for (int i = t; i < 512; i += 256) {
            int r = i >> 4, c16 = i & 15;
            uint32_t doff = (uint32_t)(r * PSQ + c16 * 16);
            cpa16(base + PG_XH + doff, xh + (size_t)r * NPOS + c16 * 8);
            cpa16(base + PG_XL + doff, xl + (size_t)r * NPOS + c16 * 8);
        }
        for (int i = t; i < 512; i += 256) {
            int r = i >> 2, c4 = i & 3;
            uint32_t doff = (uint32_t)(r * PSW + c4 * 16);
            cpa16(base + PG_WH + doff, g_WGh + (size_t)r * CIN + c4 * 8);
            cpa16(base + PG_WL + doff, g_WGl + (size_t)r * CIN + c4 * 8);
        }
        CP_COMMIT();
    }

    #pragma unroll 1
    for (int ch = 0; ch < 8; ch++) {
        if (ch < 7) {
            int c0 = (ch + 1) * 32;
            uint32_t base = sb + ((ch + 1) & 1) * PG_BUF;
            for (int i = t; i < 512; i += 256) {
                int r = i >> 4, c16 = i & 15;
                uint32_t doff = (uint32_t)(r * PSQ + c16 * 16);
                cpa16(base + PG_XH + doff, xh + (size_t)(c0 + r) * NPOS + c16 * 8);
                cpa16(base + PG_XL + doff, xl + (size_t)(c0 + r) * NPOS + c16 * 8);
            }
            for (int i = t; i < 512; i += 256) {
                int r = i >> 2, c4 = i & 3;
                uint32_t doff = (uint32_t)(r * PSW + c4 * 16);
                cpa16(base + PG_WH + doff, g_WGh + (size_t)r * CIN + c0 + c4 * 8);
                cpa16(base + PG_WL + doff, g_WGl + (size_t)r * CIN + c0 + c4 * 8);
            }
            CP_COMMIT();
            CP_WAIT1();
        } else {
            CP_WAIT0();
        }
        __syncthreads();
        const uint32_t xbase = sb + (ch & 1) * PG_BUF;
        const uint32_t aB = xbase + PG_WH + aoff;
        const uint32_t bB = xbase + PG_XH + boff;
        #pragma unroll
        for (int kk = 0; kk < 2; kk++) {
            uint32_t ah[4], al[4];
            ldsm4(ah, aB + kk * 32);
            ldsm4(al, aB + 10240 + kk * 32);
            #pragma unroll
            for (int np = 0; np < 8; np++) {
                uint32_t bh[4], bl[4];
                ldsm4t(bh, bB + np * 32 + kk * 16 * PSQ);
                ldsm4t(bl, bB + 8704 + np * 32 + kk * 16 * PSQ);
                mma16816(acc[2 * np],     ah, bh[0], bh[1]);
                mma16816(acc[2 * np + 1], ah, bh[2], bh[3]);
                mma16816(acc[2 * np],     ah, bl[0], bl[1]);
                mma16816(acc[2 * np + 1], ah, bl[2], bl[3]);
                mma16816(acc[2 * np],     al, bh[0], bh[1]);
                mma16816(acc[2 * np + 1], al, bh[2], bh[3]);
            }
        }
        __syncthreads();
    }

    const int o = 16 * w + g;
    const float b0 = bias[o], b8 = bias[o + 8];
    #pragma unroll
    for (int j = 0; j < 16; j++) {
        int n = 16 * (j >> 1) + 8 * (j & 1) + 2 * tc;
        size_t a0 = ((size_t)b * CI + o) * NPOS + n0 + n;
        size_t a8 = a0 + (size_t)8 * NPOS;
        *(uint32_t*)(g_G + a0) = pkh2(acc[j][0] + b0, acc[j][1] + b0);
        *(uint32_t*)(g_G + a8) = pkh2(acc[j][2] + b8, acc[j][3] + b8);
    }
}

// =================================================================
// K2: attention — QK bf16 3-term with RAW-chain-breaking term-major
// ordering (same-acc issue distance 4); PV fp16; W-conv fp16 full-W.
// =================================================================
#define SQ  272
#define SPG 144
#define SM_QH  0
#define SM_QL  34816
#define SM_K0  69632
#define SM_K1  104448
#define SM_G0  139264
#define SM_G1  157696
#define SMEM_BYTES 176128
#define SM_WB  69632

__global__ __launch_bounds__(256, 1) void attn_mma_kernel(const float* __restrict__ W_b)
{
    extern __shared__ __align__(16) char smem[];
    const uint32_t sb = s2u(smem);
    const int t = threadIdx.x, w = t >> 5, L = t & 31;
    const int b = blockIdx.y;
    const int q0 = blockIdx.x * 128;
    const int g  = L >> 2, tc = L & 3;

    const __nv_bfloat16* qh  = g_THh + ((size_t)b * NPOS + q0) * CI;
    const __nv_bfloat16* ql  = g_THl + ((size_t)b * NPOS + q0) * CI;
    const __nv_bfloat16* khb = g_PHh + (size_t)b * NPOS * CI;
    const __nv_bfloat16* klb = g_PHl + (size_t)b * NPOS * CI;
    const __half*        ghb = g_G + (size_t)b * CI * NPOS;

    for (int i = t; i < 2048; i += 256) {
        int r = i >> 4, c16 = i & 15;
        uint32_t doff = (uint32_t)(r * SQ + c16 * 16);
        cpa16(sb + SM_QH + doff, qh + (size_t)r * CI + c16 * 8);
        cpa16(sb + SM_QL + doff, ql + (size_t)r * CI + c16 * 8);
    }
    for (int i = t; i < 1024; i += 256) {
        int r = i >> 4, c16 = i & 15;
        uint32_t doff = (uint32_t)(r * SQ + c16 * 16);
        cpa16(sb + SM_K0 + doff, khb + (size_t)r * CI + c16 * 8);
        cpa16(sb + SM_K0 + 17408 + doff, klb + (size_t)r * CI + c16 * 8);
    }
    for (int i = t; i < 1024; i += 256) {
        int r = i >> 3, c8 = i & 7;
        cpa16(sb + SM_G0 + (uint32_t)(r * SPG + c8 * 16), ghb + (size_t)r * NPOS + c8 * 8);
    }
    CP_COMMIT();

    const int lr = ((L >> 3) & 1) * 8 + (L & 7);
    const int lk = (L >> 4) * 16;
    const int bn = (L >> 4) * 8 + (L & 7);
    const int bk = ((L >> 3) & 1) * 16;

    const uint32_t aQh = sb + SM_QH + (uint32_t)((16 * w + lr) * SQ + lk);
    const uint32_t aQl = aQh + (SM_QL - SM_QH);
    const uint32_t kOff = (uint32_t)(bn * SQ + bk);
    const uint32_t gOff = (uint32_t)(bn * SPG + bk);

    CP_WAIT0();
    __syncthreads();

    float yacc[16][4];
    #pragma unroll
    for (int n = 0; n < 16; n++)
        #pragma unroll
        for (int j = 0; j < 4; j++) yacc[n][j] = 0.f;
    float ls0 = 0.f, ls1 = 0.f;
    float m0 = -INFINITY, m1 = -INFINITY;

    #pragma unroll 1
    for (int mt = 0; mt < NPOS / 64; mt++) {
        if (mt > 0) {
            CP_WAIT0();
            __syncthreads();
        }

        if (mt < 63) {
            const int m1i = mt * 64 + 64;
            const uint32_t kdst = sb + (((mt + 1) & 1) ? SM_K1 : SM_K0);
            const uint32_t gdst = sb + (((mt + 1) & 1) ? SM_G1 : SM_G0);
            for (int i = t; i < 1024; i += 256) {
                int r = i >> 4, c16 = i & 15;
                uint32_t doff = (uint32_t)(r * SQ + c16 * 16);
                cpa16(kdst + doff, khb + (size_t)(m1i + r) * CI + c16 * 8);
                cpa16(kdst + 17408 + doff, klb + (size_t)(m1i + r) * CI + c16 * 8);
            }
            for (int i = t; i < 1024; i += 256) {
                int r = i >> 3, c8 = i & 7;
                cpa16(gdst + (uint32_t)(r * SPG + c8 * 16),
                      ghb + (size_t)r * NPOS + m1i + c8 * 8);
            }
            CP_COMMIT();
        }

        // ---- QK: bf16 3-term, term-major per np-pair (RAW distance 4) ----
        const uint32_t bKh = sb + ((mt & 1) ? SM_K1 : SM_K0) + kOff;
        const uint32_t bKl = bKh + 17408;
        float acc[8][4];
        #pragma unroll
        for (int n = 0; n < 8; n++)
            #pragma unroll
            for (int j = 0; j < 4; j++) acc[n][j] = 0.f;
        #pragma unroll
        for (int kk = 0; kk < 8; kk++) {
            uint32_t ah[4], al[4];
            ldsm4(ah, aQh + kk * 32);
            ldsm4(al, aQl + kk * 32);
            #pragma unroll
            for (int pp = 0; pp < 2; pp++) {      // np pairs {0,1}, {2,3}
                const int n0i = pp * 4;           // acc base
                uint32_t b0h[4], b0l[4], b1h[4], b1l[4];
                ldsm4(b0h, bKh + (2 * pp) * (16 * SQ) + kk * 32);
                ldsm4(b0l, bKl + (2 * pp) * (16 * SQ) + kk * 32);
                ldsm4(b1h, bKh + (2 * pp + 1) * (16 * SQ) + kk * 32);
                ldsm4(b1l, bKl + (2 * pp + 1) * (16 * SQ) + kk * 32);
                // term hh
                mma16816(acc[n0i],     ah, b0h[0], b0h[1]);
                mma16816(acc[n0i + 1], ah, b0h[2], b0h[3]);
                mma16816(acc[n0i + 2], ah, b1h[0], b1h[1]);
                mma16816(acc[n0i + 3], ah, b1h[2], b1h[3]);
                // term hl
                mma16816(acc[n0i],     ah, b0l[0], b0l[1]);
                mma16816(acc[n0i + 1], ah, b0l[2], b0l[3]);
                mma16816(acc[n0i + 2], ah, b1l[0], b1l[1]);
                mma16816(acc[n0i + 3], ah, b1l[2], b1l[3]);
                // term lh
                mma16816(acc[n0i],     al, b0h[0], b0h[1]);
                mma16816(acc[n0i + 1], al, b0h[2], b0h[3]);
                mma16816(acc[n0i + 2], al, b1h[0], b1h[1]);
                mma16816(acc[n0i + 3], al, b1h[2], b1h[3]);
            }
        }

        // ---- flash online-max softmax (skip-rescale vote) ----
        float tm0 = -INFINITY, tm1 = -INFINITY;
        #pragma unroll
        for (int n = 0; n < 8; n++) {
            tm0 = fmaxf(tm0, fmaxf(acc[n][0], acc[n][1]));
            tm1 = fmaxf(tm1, fmaxf(acc[n][2], acc[n][3]));
        }
        tm0 = fmaxf(tm0, __shfl_xor_sync(0xffffffffu, tm0, 1));
        tm0 = fmaxf(tm0, __shfl_xor_sync(0xffffffffu, tm0, 2));
        tm1 = fmaxf(tm1, __shfl_xor_sync(0xffffffffu, tm1, 1));
        tm1 = fmaxf(tm1, __shfl_xor_sync(0xffffffffu, tm1, 2));
        bool noup = (tm0 <= m0) && (tm1 <= m1);
        if (!__all_sync(0xffffffffu, noup)) {
            float mn0 = fmaxf(m0, tm0), mn1 = fmaxf(m1, tm1);
            float al0 = __expf(m0 - mn0), al1 = __expf(m1 - mn1);
            m0 = mn0; m1 = mn1;
            ls0 *= al0; ls1 *= al1;
            #pragma unroll
            for (int n = 0; n < 16; n++) {
                yacc[n][0] *= al0; yacc[n][1] *= al0;
                yacc[n][2] *= al1; yacc[n][3] *= al1;
            }
        }

        uint32_t pf[4][4];
        #pragma unroll
        for (int n = 0; n < 8; n++) {
            float p0 = __expf(acc[n][0] - m0);
            float p1 = __expf(acc[n][1] - m0);
            float p2 = __expf(acc[n][2] - m1);
            float p3 = __expf(acc[n][3] - m1);
            ls0 += p0 + p1;
            ls1 += p2 + p3;
            int kk = n >> 1, e = (n & 1) * 2;
            pf[kk][e]     = pkh2(p0, p1);
            pf[kk][e + 1] = pkh2(p2, p3);
        }

        // ---- PV (fp16 single term) ----
        const uint32_t bG = sb + ((mt & 1) ? SM_G1 : SM_G0) + gOff;
        #pragma unroll
        for (int kk = 0; kk < 4; kk++) {
            #pragma unroll
            for (int np = 0; np < 8; np++) {
                uint32_t bh[4];
                ldsm4(bh, bG + np * (16 * SPG) + kk * 32);
                mma16816h(yacc[2 * np],     pf[kk], bh[0], bh[1]);
                mma16816h(yacc[2 * np + 1], pf[kk], bh[2], bh[3]);
            }
        }
    }

    // ---- finalize row sums ----
    ls0 += __shfl_xor_sync(0xffffffffu, ls0, 1);
    ls0 += __shfl_xor_sync(0xffffffffu, ls0, 2);
    ls1 += __shfl_xor_sync(0xffffffffu, ls1, 1);
    ls1 += __shfl_xor_sync(0xffffffffu, ls1, 2);

    uint32_t yf[8][4];
    {
        float rv0 = 1.f / ls0, rv1 = 1.f / ls1;
        #pragma unroll
        for (int n = 0; n < 16; n++) {
            int kk = n >> 1, e = (n & 1) * 2;
            yf[kk][e]     = pkh2(yacc[n][0] * rv0, yacc[n][1] * rv0);
            yf[kk][e + 1] = pkh2(yacc[n][2] * rv1, yacc[n][3] * rv1);
        }
    }

    // ---- WY = W_w @ Y + W_b : stage FULL 256-row W once ----
    __syncthreads();
    for (int i = t; i < 4096; i += 256) {
        int r = i >> 4, c16 = i & 15;
        *(uint4*)(smem + SM_WB + (uint32_t)(r * SQ + c16 * 16)) =
            *(const uint4*)(g_Whalf + (size_t)r * CI + c16 * 8);
    }
    __syncthreads();

    const uint32_t bW = sb + SM_WB + (uint32_t)(bn * SQ + bk);
    float* WYb = g_WY + (size_t)b * CIN * NPOS + q0;

    #pragma unroll 1
    for (int h = 0; h < 2; h++) {
        const uint32_t bWh_ = bW + (uint32_t)(h * 128 * SQ);
        float wacc[16][4];
        #pragma unroll
        for (int n = 0; n < 16; n++)
            #pragma unroll
            for (int j = 0; j < 4; j++) wacc[n][j] = 0.f;

        #pragma unroll
        for (int kk = 0; kk < 8; kk++) {
            #pragma unroll
            for (int np = 0; np < 8; np++) {
                uint32_t bh[4];
                ldsm4(bh, bWh_ + np * (16 * SQ) + kk * 32);
                mma16816h(wacc[2 * np],     yf[kk], bh[0], bh[1]);
                mma16816h(wacc[2 * np + 1], yf[kk], bh[2], bh[3]);
            }
        }

        #pragma unroll
        for (int n = 0; n < 16; n++) {
            int o = h * 128 + 8 * n + 2 * tc;
            float b0 = __ldg(&W_b[o]);
            float b1 = __ldg(&W_b[o + 1]);
            int r0 = 16 * w + g;
            WYb[(size_t)o * NPOS + r0]           = wacc[n][0] + b0;
            WYb[(size_t)(o + 1) * NPOS + r0]     = wacc[n][1] + b1;
            WYb[(size_t)o * NPOS + r0 + 8]       = wacc[n][2] + b0;
            WYb[(size_t)(o + 1) * NPOS + r0 + 8] = wacc[n][3] + b1;
        }
    }
}

// =================================================================
// K3: BN statistics — partial pass + finalize
// =================================================================
__global__ __launch_bounds__(256) void stats_part_kernel()
{
    const int c = blockIdx.x;
    const int s = blockIdx.y;
    const int t = threadIdx.x;
    float sm = 0.f, ss = 0.f;
    for (int b = 2 * s; b < 2 * s + 2; b++) {
        const float* p = g_WY + ((size_t)b * CIN + c) * NPOS;
        for (int i = t; i < NPOS / 4; i += 256) {
            float4 v = *(const float4*)&p[4 * i];
            sm += v.x + v.y + v.z + v.w;
            ss += v.x * v.x + v.y * v.y + v.z * v.z + v.w * v.w;
        }
    }
    __shared__ float rs[256], rss[256];
    rs[t] = sm; rss[t] = ss;
    __syncthreads();
    for (int o = 128; o > 0; o >>= 1) {
        if (t < o) { rs[t] += rs[t + o]; rss[t] += rss[t + o]; }
        __syncthreads();
    }
    if (t == 0) {
        g_ps[s * CIN + c]  = rs[0];
        g_pss[s * CIN + c] = rss[0];
    }
}

__global__ __launch_bounds__(256) void stats_fin_kernel()
{
    const int c = threadIdx.x;
    float sm = g_ps[c] + g_ps[CIN + c] + g_ps[2 * CIN + c] + g_ps[3 * CIN + c];
    float ss = g_pss[c] + g_pss[CIN + c] + g_pss[2 * CIN + c] + g_pss[3 * CIN + c];
    const float inv = 1.f / (float)(BATCH * NPOS);
    float mean = sm * inv;
    float var  = ss * inv - mean * mean;
    g_mean[c] = mean;
    g_rstd[c] = rsqrtf(var + 1e-5f);
}

// =================================================================
// K4: z = (wy - mean)*rstd*gamma + beta + x
// =================================================================
__global__ __launch_bounds__(256) void final_kernel(
    const float* __restrict__ x,
    const float* __restrict__ gamma, const float* __restrict__ beta,
    float* __restrict__ z)
{
    size_t i4 = (size_t)blockIdx.x * 256 + threadIdx.x;
    size_t i  = i4 * 4;
    int c = (int)((i >> 12) & 255);
    float m = g_mean[c], r = g_rstd[c], ga = gamma[c], be = beta[c];
    float4 wy = *(const float4*)&g_WY[i];
    float4 xv = *(const float4*)&x[i];
    float4 o;
    o.x = (wy.x - m) * r * ga + be + xv.x;
    o.y = (wy.y - m) * r * ga + be + xv.y;
    o.z = (wy.z - m) * r * ga + be + xv.z;
    o.w = (wy.w - m) * r * ga + be + xv.w;
    *(float4*)&z[i] = o;
}

// =================================================================
extern "C" void kernel_launch(void* const* d_in, const int* in_sizes, int n_in,
                              void* d_out, int out_size)
{
    const float* x       = (const float*)d_in[0];
    const float* g_w     = (const float*)d_in[1];
    const float* g_b     = (const float*)d_in[2];
    const float* theta_w = (const float*)d_in[3];
    const float* theta_b = (const float*)d_in[4];
    const float* phi_w   = (const float*)d_in[5];
    const float* phi_b   = (const float*)d_in[6];
    const float* W_w     = (const float*)d_in[7];
    const float* W_b     = (const float*)d_in[8];
    const float* bn_g    = (const float*)d_in[9];
    const float* bn_b    = (const float*)d_in[10];
    float* z = (float*)d_out;

    cudaFuncSetAttribute(proj_npos_kernel, cudaFuncAttributeMaxDynamicSharedMemorySize, PN_SMEM);
    cudaFuncSetAttribute(proj_chan_kernel, cudaFuncAttributeMaxDynamicSharedMemorySize, PG_SMEM);
    cudaFuncSetAttribute(attn_mma_kernel,  cudaFuncAttributeMaxDynamicSharedMemorySize, SMEM_BYTES);

    split_all_kernel<<<8704, 256>>>(x, theta_w, phi_w, g_w, W_w);
    proj_npos_kernel<<<dim3(32, 8, 2), 256, PN_SMEM>>>(theta_b, phi_b);
    proj_chan_kernel<<<dim3(32, 8), 256, PG_SMEM>>>(g_b);
    attn_mma_kernel<<<dim3(32, 8), 256, SMEM_BYTES>>>(W_b);
    stats_part_kernel<<<dim3(256, 4), 256>>>();
    stats_fin_kernel<<<1, 256>>>();
    final_kernel<<<8192, 256>>>(x, bn_g, bn_b, z);
}

// round 15
// speedup vs baseline: 1.0155x; 1.0067x over previous
#include <cuda_runtime.h>
#include <cuda_bf16.h>
#include <cuda_fp16.h>
#include <math.h>
#include <stdint.h>

#define BATCH 8
#define CIN   256
#define CI    128
#define NPOS  4096

// ---------------- scratch (allocation-free: __device__ globals) ----------------
__device__ __align__(16) __nv_bfloat16 g_THh[(size_t)BATCH * NPOS * CI];
__device__ __align__(16) __nv_bfloat16 g_THl[(size_t)BATCH * NPOS * CI];
__device__ __align__(16) __nv_bfloat16 g_PHh[(size_t)BATCH * NPOS * CI];
__device__ __align__(16) __nv_bfloat16 g_PHl[(size_t)BATCH * NPOS * CI];
__device__ __align__(16) __half        g_G  [(size_t)BATCH * CI * NPOS];
__device__ __align__(16) __nv_bfloat16 g_WQh[2 * CI * CIN];
__device__ __align__(16) __nv_bfloat16 g_WQl[2 * CI * CIN];
__device__ __align__(16) __nv_bfloat16 g_WGh[CI * CIN];
__device__ __align__(16) __nv_bfloat16 g_WGl[CI * CIN];
__device__ __align__(16) __half        g_Whalf[CIN * CI];
__device__ float g_WY[(size_t)BATCH * CIN * NPOS];
__device__ float g_ps[4 * CIN], g_pss[4 * CIN];
__device__ float g_mean[CIN];
__device__ float g_rstd[CIN];

// ---------------- helpers ----------------
__device__ __forceinline__ uint32_t s2u(const void* p) {
    uint32_t a;
    asm("{ .reg .u64 t; cvta.to.shared.u64 t, %1; cvt.u32.u64 %0, t; }" : "=r"(a) : "l"(p));
    return a;
}
__device__ __forceinline__ void ldsm4(uint32_t r[4], uint32_t addr) {
    asm volatile("ldmatrix.sync.aligned.m8n8.x4.shared.b16 {%0,%1,%2,%3}, [%4];"
                 : "=r"(r[0]), "=r"(r[1]), "=r"(r[2]), "=r"(r[3]) : "r"(addr));
}
__device__ __forceinline__ void ldsm4t(uint32_t r[4], uint32_t addr) {
    asm volatile("ldmatrix.sync.aligned.m8n8.x4.trans.shared.b16 {%0,%1,%2,%3}, [%4];"
                 : "=r"(r[0]), "=r"(r[1]), "=r"(r[2]), "=r"(r[3]) : "r"(addr));
}
__device__ __forceinline__ void mma16816(float d[4], const uint32_t a[4],
                                         uint32_t b0, uint32_t b1) {
    asm volatile(
        "mma.sync.aligned.m16n8k16.row.col.f32.bf16.bf16.f32 "
        "{%0,%1,%2,%3}, {%4,%5,%6,%7}, {%8,%9}, {%0,%1,%2,%3};"
        : "+f"(d[0]), "+f"(d[1]), "+f"(d[2]), "+f"(d[3])
        : "r"(a[0]), "r"(a[1]), "r"(a[2]), "r"(a[3]), "r"(b0), "r"(b1));
}
__device__ __forceinline__ void mma16816h(float d[4], const uint32_t a[4],
                                          uint32_t b0, uint32_t b1) {
    asm volatile(
        "mma.sync.aligned.m16n8k16.row.col.f32.f16.f16.f32 "
        "{%0,%1,%2,%3}, {%4,%5,%6,%7}, {%8,%9}, {%0,%1,%2,%3};"
        : "+f"(d[0]), "+f"(d[1]), "+f"(d[2]), "+f"(d[3])
        : "r"(a[0]), "r"(a[1]), "r"(a[2]), "r"(a[3]), "r"(b0), "r"(b1));
}
__device__ __forceinline__ void cpa16(uint32_t dst, const void* src) {
    asm volatile("cp.async.cg.shared.global [%0], [%1], 16;" :: "r"(dst), "l"(src));
}
#define CP_COMMIT() asm volatile("cp.async.commit_group;" ::: "memory")
#define CP_WAIT0()  asm volatile("cp.async.wait_group 0;" ::: "memory")
#define CP_WAIT1()  asm volatile("cp.async.wait_group 1;" ::: "memory")

__device__ __forceinline__ uint32_t pkbf(float a, float b, float* ra, float* rb) {
    __nv_bfloat162 h2 = __floats2bfloat162_rn(a, b);
    uint32_t u = *reinterpret_cast<uint32_t*>(&h2);
    *ra = a - __uint_as_float(u << 16);
    *rb = b - __uint_as_float(u & 0xffff0000u);
    return u;
}
__device__ __forceinline__ uint32_t pkbf2(float a, float b) {
    __nv_bfloat162 h2 = __floats2bfloat162_rn(a, b);
    return *reinterpret_cast<uint32_t*>(&h2);
}
__device__ __forceinline__ uint32_t pkh2(float a, float b) {
    __half2 h2 = __floats2half2_rn(a, b);
    return *reinterpret_cast<uint32_t*>(&h2);
}

// =================================================================
// K0: split WEIGHTS only (x is now converted inside the proj kernel)
// =================================================================
__global__ __launch_bounds__(256) void split_wts_kernel(
    const float* __restrict__ thw, const float* __restrict__ phw,
    const float* __restrict__ gw,  const float* __restrict__ Ww)
{
    int i = blockIdx.x * 256 + threadIdx.x;   // 0..131071
    int which = i >> 15, j = i & 32767;
    if (which == 3) { g_Whalf[j] = __float2half(Ww[j]); return; }
    float v;
    __nv_bfloat16 *dh, *dl;
    int o;
    if (which == 0)      { v = thw[j]; dh = g_WQh; dl = g_WQl; o = j; }
    else if (which == 1) { v = phw[j]; dh = g_WQh; dl = g_WQl; o = 32768 + j; }
    else                 { v = gw[j];  dh = g_WGh; dl = g_WGl; o = j; }
    __nv_bfloat16 h = __float2bfloat16(v);
    dh[o] = h;
    dl[o] = __float2bfloat16(v - __bfloat162float(h));
}

// =================================================================
// K1: ALL projections fused. blockIdx.z: 0 theta, 1 phi, 2 g.
// x read as fp32, split to bf16 hi/lo in-kernel (reg-staged pipeline).
// 128n x 128o per CTA, K=256 in 8 chunks of 32, W double-buffered.
// =================================================================
#define PSQ 272
#define PSW 80
#define PA_XH 0
#define PA_XL 8704
#define PA_WH 17408
#define PA_WL 27648
#define PA_BUF 37888
#define PA_BIAS 75776
#define PA_SMEM 76800

__device__ __forceinline__ void cvt_sts_x(char* smem, uint32_t bufbase, int t,
                                          const float4 xr[4])
{
    const float* f = (const float*)xr;
    uint32_t h[8], l[8];
    #pragma unroll
    for (int p = 0; p < 8; p++) {
        float r0, r1;
        h[p] = pkbf(f[2 * p], f[2 * p + 1], &r0, &r1);
        l[p] = pkbf2(r0, r1);
    }
    uint32_t off = (uint32_t)((t >> 3) * PSQ + (t & 7) * 32);
    *(uint4*)(smem + bufbase + PA_XH + off)      = make_uint4(h[0], h[1], h[2], h[3]);
    *(uint4*)(smem + bufbase + PA_XH + off + 16) = make_uint4(h[4], h[5], h[6], h[7]);
    *(uint4*)(smem + bufbase + PA_XL + off)      = make_uint4(l[0], l[1], l[2], l[3]);
    *(uint4*)(smem + bufbase + PA_XL + off + 16) = make_uint4(l[4], l[5], l[6], l[7]);
}

__global__ __launch_bounds__(256, 2) void proj_all_kernel(
    const float* __restrict__ x,
    const float* __restrict__ th_b, const float* __restrict__ ph_b,
    const float* __restrict__ g_b)
{
    extern __shared__ __align__(16) char smem[];
    const uint32_t sb = s2u(smem);
    const int t = threadIdx.x, w = t >> 5, L = t & 31;
    const int g = L >> 2, tc = L & 3;
    const int b = blockIdx.y;
    const int n0 = blockIdx.x * 128;
    const int z = blockIdx.z;          // 0 theta, 1 phi, 2 g

    float* bias = (float*)(smem + PA_BIAS);
    if (t < 128) bias[t] = (z == 0) ? th_b[t] : (z == 1) ? ph_b[t] : g_b[t];

    const float* xf = x + (size_t)b * CIN * NPOS + n0;
    const __nv_bfloat16* wh = (z < 2) ? (g_WQh + (size_t)z * 32768) : g_WGh;
    const __nv_bfloat16* wl = (z < 2) ? (g_WQl + (size_t)z * 32768) : g_WGl;

    // x pipeline: thread covers row (t>>3) of 32, cols (t&7)*16..+16 of 128
    const int xrow = t >> 3;
    const int xcol = (t & 7) * 16;

    float acc[16][4];
    #pragma unroll
    for (int j = 0; j < 16; j++)
        #pragma unroll
        for (int k = 0; k < 4; k++) acc[j][k] = 0.f;

    float4 xr[4];
    // prologue: LDG x(0) -> convert/STS into buf0; LDG x(1); cp.async W(0)
    #pragma unroll
    for (int j = 0; j < 4; j++)
        xr[j] = *(const float4*)&xf[(size_t)xrow * NPOS + xcol + 4 * j];
    cvt_sts_x(smem, 0, t, xr);
    #pragma unroll
    for (int j = 0; j < 4; j++)
        xr[j] = *(const float4*)&xf[(size_t)(32 + xrow) * NPOS + xcol + 4 * j];
    for (int i = t; i < 512; i += 256) {
        int r = i >> 2, c4 = i & 3;
        uint32_t doff = (uint32_t)(r * PSW + c4 * 16);
        cpa16(sb + PA_WH + doff, wh + (size_t)r * CIN + c4 * 8);
        cpa16(sb + PA_WL + doff, wl + (size_t)r * CIN + c4 * 8);
    }
    CP_COMMIT();

    // lane offsets (both orientations)
    const uint32_t aoffN = (uint32_t)(((L & 7) + ((L >> 4) & 1) * 8) * PSQ + 32 * w +
                                      ((L >> 3) & 1) * 16);
    const uint32_t boffN = (uint32_t)(((L >> 4) * 8 + (L & 7)) * PSW + ((L >> 3) & 1) * 16);
    const uint32_t aoffG = (uint32_t)((16 * w + (L & 7) + ((L >> 3) & 1) * 8) * PSW +
                                      (L >> 4) * 16);
    const uint32_t boffG = (uint32_t)(((L & 7) + ((L >> 3) & 1) * 8) * PSQ + (L >> 4) * 16);

    #pragma unroll 1
    for (int ch = 0; ch < 8; ch++) {
        if (ch < 7) {
            int c0 = (ch + 1) * 32;
            uint32_t base = sb + ((ch + 1) & 1) * PA_BUF;
            for (int i = t; i < 512; i += 256) {
                int r = i >> 2, c4 = i & 3;
                uint32_t doff = (uint32_t)(r * PSW + c4 * 16);
                cpa16(base + PA_WH + doff, wh + (size_t)r * CIN + c0 + c4 * 8);
                cpa16(base + PA_WL + doff, wl + (size_t)r * CIN + c0 + c4 * 8);
            }
            CP_COMMIT();
            CP_WAIT1();
        } else {
            CP_WAIT0();
        }
        __syncthreads();   // buf[ch&1] X (STS'd earlier) + W (cp.async) ready

        // store x(ch+1) into buf[(ch+1)&1]; then prefetch x(ch+2) regs
        if (ch < 7) {
            cvt_sts_x(smem, (uint32_t)(((ch + 1) & 1) * PA_BUF), t, xr);
            if (ch < 6) {
                const size_t rbase = (size_t)((ch + 2) * 32 + xrow) * NPOS + xcol;
                #pragma unroll
                for (int j = 0; j < 4; j++)
                    xr[j] = *(const float4*)&xf[rbase + 4 * j];
            }
        }

        const uint32_t xbase = sb + (ch & 1) * PA_BUF;
        if (z < 2) {
            const uint32_t aB = xbase + PA_XH + aoffN;
            const uint32_t bB = xbase + PA_WH + boffN;
            #pragma unroll
            for (int kk = 0; kk < 2; kk++) {
                uint32_t ah[4], al[4];
                ldsm4t(ah, aB + kk * 16 * PSQ);
                ldsm4t(al, aB + 8704 + kk * 16 * PSQ);
                #pragma unroll
                for (int np = 0; np < 8; np++) {
                    uint32_t bh[4], bl[4];
                    ldsm4(bh, bB + np * (16 * PSW) + kk * 32);
                    ldsm4(bl, bB + 10240 + np * (16 * PSW) + kk * 32);
                    mma16816(acc[2 * np],     ah, bh[0], bh[1]);
                    mma16816(acc[2 * np + 1], ah, bh[2], bh[3]);
                    mma16816(acc[2 * np],     ah, bl[0], bl[1]);
                    mma16816(acc[2 * np + 1], ah, bl[2], bl[3]);
                    mma16816(acc[2 * np],     al, bh[0], bh[1]);
                    mma16816(acc[2 * np + 1], al, bh[2], bh[3]);
                }
            }
        } else {
            const uint32_t aB = xbase + PA_WH + aoffG;
            const uint32_t bB = xbase + PA_XH + boffG;
            #pragma unroll
            for (int kk = 0; kk < 2; kk++) {
                uint32_t ah[4], al[4];
                ldsm4(ah, aB + kk * 32);
                ldsm4(al, aB + 10240 + kk * 32);
                #pragma unroll
                for (int np = 0; np < 8; np++) {
                    uint32_t bh[4], bl[4];
                    ldsm4t(bh, bB + np * 32 + kk * 16 * PSQ);
                    ldsm4t(bl, bB + 8704 + np * 32 + kk * 16 * PSQ);
                    mma16816(acc[2 * np],     ah, bh[0], bh[1]);
                    mma16816(acc[2 * np + 1], ah, bh[2], bh[3]);
                    mma16816(acc[2 * np],     ah, bl[0], bl[1]);
                    mma16816(acc[2 * np + 1], ah, bl[2], bl[3]);
                    mma16816(acc[2 * np],     al, bh[0], bh[1]);
                    mma16816(acc[2 * np + 1], al, bh[2], bh[3]);
                }
            }
        }
        __syncthreads();
    }

    if (z < 2) {
        const int nrow = n0 + 16 * w + g;
        const size_t rb0 = ((size_t)b * NPOS + nrow) * CI;
        const size_t rb1 = rb0 + (size_t)8 * CI;
        __nv_bfloat16* dh = z ? g_PHh : g_THh;
        __nv_bfloat16* dl = z ? g_PHl : g_THl;
        #pragma unroll
        for (int j = 0; j < 16; j++) {
            int o = 8 * j + 2 * tc;
            float b0 = bias[o], b1 = bias[o + 1];
            float r0, r1;
            uint32_t hp = pkbf(acc[j][0] + b0, acc[j][1] + b1, &r0, &r1);
            uint32_t lp = pkbf2(r0, r1);
            *(uint32_t*)(dh + rb0 + o) = hp;
            *(uint32_t*)(dl + rb0 + o) = lp;
            hp = pkbf(acc[j][2] + b0, acc[j][3] + b1, &r0, &r1);
            lp = pkbf2(r0, r1);
            *(uint32_t*)(dh + rb1 + o) = hp;
            *(uint32_t*)(dl + rb1 + o) = lp;
        }
    } else {
        const int o = 16 * w + g;
        const float b0 = bias[o], b8 = bias[o + 8];
        #pragma unroll
        for (int j = 0; j < 16; j++) {
            int n = 16 * (j >> 1) + 8 * (j & 1) + 2 * tc;
            size_t a0 = ((size_t)b * CI + o) * NPOS + n0 + n;
            size_t a8 = a0 + (size_t)8 * NPOS;
            *(uint32_t*)(g_G + a0) = pkh2(acc[j][0] + b0, acc[j][1] + b0);
            *(uint32_t*)(g_G + a8) = pkh2(acc[j][2] + b8, acc[j][3] + b8);
        }
    }
}

// =================================================================
// K2: attention — QK bf16 3-term (Q resident), PV fp16 (flash online max),
// W-conv fp16 full-W staging.  (R12 structure.)
// =================================================================
#define SQ  272
#define SPG 144
#define SM_QH  0
#define SM_QL  34816
#define SM_K0  69632
#define SM_K1  104448
#define SM_G0  139264
#define SM_G1  157696
#define SMEM_BYTES 176128
#define SM_WB  69632

__global__ __launch_bounds__(256, 1) void attn_mma_kernel(const float* __restrict__ W_b)
{
    extern __shared__ __align__(16) char smem[];
    const uint32_t sb = s2u(smem);
    const int t = threadIdx.x, w = t >> 5, L = t & 31;
    const int b = blockIdx.y;
    const int q0 = blockIdx.x * 128;
    const int g  = L >> 2, tc = L & 3;

    const __nv_bfloat16* qh  = g_THh + ((size_t)b * NPOS + q0) * CI;
    const __nv_bfloat16* ql  = g_THl + ((size_t)b * NPOS + q0) * CI;
    const __nv_bfloat16* khb = g_PHh + (size_t)b * NPOS * CI;
    const __nv_bfloat16* klb = g_PHl + (size_t)b * NPOS * CI;
    const __half*        ghb = g_G + (size_t)b * CI * NPOS;

    for (int i = t; i < 2048; i += 256) {
        int r = i >> 4, c16 = i & 15;
        uint32_t doff = (uint32_t)(r * SQ + c16 * 16);
        cpa16(sb + SM_QH + doff, qh + (size_t)r * CI + c16 * 8);
        cpa16(sb + SM_QL + doff, ql + (size_t)r * CI + c16 * 8);
    }
    for (int i = t; i < 1024; i += 256) {
        int r = i >> 4, c16 = i & 15;
        uint32_t doff = (uint32_t)(r * SQ + c16 * 16);
        cpa16(sb + SM_K0 + doff, khb + (size_t)r * CI + c16 * 8);
        cpa16(sb + SM_K0 + 17408 + doff, klb + (size_t)r * CI + c16 * 8);
    }
    for (int i = t; i < 1024; i += 256) {
        int r = i >> 3, c8 = i & 7;
        cpa16(sb + SM_G0 + (uint32_t)(r * SPG + c8 * 16), ghb + (size_t)r * NPOS + c8 * 8);
    }
    CP_COMMIT();

    const int lr = ((L >> 3) & 1) * 8 + (L & 7);
    const int lk = (L >> 4) * 16;
    const int bn = (L >> 4) * 8 + (L & 7);
    const int bk = ((L >> 3) & 1) * 16;

    const uint32_t aQh = sb + SM_QH + (uint32_t)((16 * w + lr) * SQ + lk);
    const uint32_t aQl = aQh + (SM_QL - SM_QH);
    const uint32_t kOff = (uint32_t)(bn * SQ + bk);
    const uint32_t gOff = (uint32_t)(bn * SPG + bk);

    CP_WAIT0();
    __syncthreads();
    uint32_t qfh[8][4], qfl[8][4];
    #pragma unroll
    for (int kk = 0; kk < 8; kk++) {
        ldsm4(qfh[kk], aQh + kk * 32);
        ldsm4(qfl[kk], aQl + kk * 32);
    }

    float yacc[16][4];
    #pragma unroll
    for (int n = 0; n < 16; n++)
        #pragma unroll
        for (int j = 0; j < 4; j++) yacc[n][j] = 0.f;
    float ls0 = 0.f, ls1 = 0.f;
    float m0 = -INFINITY, m1 = -INFINITY;

    #pragma unroll 1
    for (int mt = 0; mt < NPOS / 64; mt++) {
        if (mt > 0) {
            CP_WAIT0();
            __syncthreads();
        }

        if (mt < 63) {
            const int m1i = mt * 64 + 64;
            const uint32_t kdst = sb + (((mt + 1) & 1) ? SM_K1 : SM_K0);
            const uint32_t gdst = sb + (((mt + 1) & 1) ? SM_G1 : SM_G0);
            for (int i = t; i < 1024; i += 256) {
                int r = i >> 4, c16 = i & 15;
                uint32_t doff = (uint32_t)(r * SQ + c16 * 16);
                cpa16(kdst + doff, khb + (size_t)(m1i + r) * CI + c16 * 8);
                cpa16(kdst + 17408 + doff, klb + (size_t)(m1i + r) * CI + c16 * 8);
            }
            for (int i = t; i < 1024; i += 256) {
                int r = i >> 3, c8 = i & 7;
                cpa16(gdst + (uint32_t)(r * SPG + c8 * 16),
                      ghb + (size_t)r * NPOS + m1i + c8 * 8);
            }
            CP_COMMIT();
        }

        // ---- QK: bf16 3-term ----
        const uint32_t bKh = sb + ((mt & 1) ? SM_K1 : SM_K0) + kOff;
        const uint32_t bKl = bKh + 17408;
        float acc[8][4];
        #pragma unroll
        for (int n = 0; n < 8; n++)
            #pragma unroll
            for (int j = 0; j < 4; j++) acc[n][j] = 0.f;
        #pragma unroll
        for (int kk = 0; kk < 8; kk++) {
            #pragma unroll
            for (int np = 0; np < 4; np++) {
                uint32_t bh[4], bl[4];
                ldsm4(bh, bKh + np * (16 * SQ) + kk * 32);
                ldsm4(bl, bKl + np * (16 * SQ) + kk * 32);
                mma16816(acc[2 * np],     qfh[kk], bh[0], bh[1]);
                mma16816(acc[2 * np + 1], qfh[kk], bh[2], bh[3]);
                mma16816(acc[2 * np],     qfh[kk], bl[0], bl[1]);
                mma16816(acc[2 * np + 1], qfh[kk], bl[2], bl[3]);
                mma16816(acc[2 * np],     qfl[kk], bh[0], bh[1]);
                mma16816(acc[2 * np + 1], qfl[kk], bh[2], bh[3]);
            }
        }

        // ---- flash online-max softmax (skip-rescale vote) ----
        float tm0 = -INFINITY, tm1 = -INFINITY;
        #pragma unroll
        for (int n = 0; n < 8; n++) {
            tm0 = fmaxf(tm0, fmaxf(acc[n][0], acc[n][1]));
            tm1 = fmaxf(tm1, fmaxf(acc[n][2], acc[n][3]));
        }
        tm0 = fmaxf(tm0, __shfl_xor_sync(0xffffffffu, tm0, 1));
        tm0 = fmaxf(tm0, __shfl_xor_sync(0xffffffffu, tm0, 2));
        tm1 = fmaxf(tm1, __shfl_xor_sync(0xffffffffu, tm1, 1));
        tm1 = fmaxf(tm1, __shfl_xor_sync(0xffffffffu, tm1, 2));
        bool noup = (tm0 <= m0) && (tm1 <= m1);
        if (!__all_sync(0xffffffffu, noup)) {
            float mn0 = fmaxf(m0, tm0), mn1 = fmaxf(m1, tm1);
            float al0 = __expf(m0 - mn0), al1 = __expf(m1 - mn1);
            m0 = mn0; m1 = mn1;
            ls0 *= al0; ls1 *= al1;
            #pragma unroll
            for (int n = 0; n < 16; n++) {
                yacc[n][0] *= al0; yacc[n][1] *= al0;
                yacc[n][2] *= al1; yacc[n][3] *= al1;
            }
        }

        uint32_t pf[4][4];
        #pragma unroll
        for (int n = 0; n < 8; n++) {
            float p0 = __expf(acc[n][0] - m0);
            float p1 = __expf(acc[n][1] - m0);
            float p2 = __expf(acc[n][2] - m1);
            float p3 = __expf(acc[n][3] - m1);
            ls0 += p0 + p1;
            ls1 += p2 + p3;
            int kk = n >> 1, e = (n & 1) * 2;
            pf[kk][e]     = pkh2(p0, p1);
            pf[kk][e + 1] = pkh2(p2, p3);
        }

        // ---- PV (fp16 single term) ----
        const uint32_t bG = sb + ((mt & 1) ? SM_G1 : SM_G0) + gOff;
        #pragma unroll
        for (int kk = 0; kk < 4; kk++) {
            #pragma unroll
            for (int np = 0; np < 8; np++) {
                uint32_t bh[4];
                ldsm4(bh, bG + np * (16 * SPG) + kk * 32);
                mma16816h(yacc[2 * np],     pf[kk], bh[0], bh[1]);
                mma16816h(yacc[2 * np + 1], pf[kk], bh[2], bh[3]);
            }
        }
    }

    // ---- finalize row sums ----
    ls0 += __shfl_xor_sync(0xffffffffu, ls0, 1);
    ls0 += __shfl_xor_sync(0xffffffffu, ls0, 2);
    ls1 += __shfl_xor_sync(0xffffffffu, ls1, 1);
    ls1 += __shfl_xor_sync(0xffffffffu, ls1, 2);

    uint32_t yf[8][4];
    {
        float rv0 = 1.f / ls0, rv1 = 1.f / ls1;
        #pragma unroll
        for (int n = 0; n < 16; n++) {
            int kk = n >> 1, e = (n & 1) * 2;
            yf[kk][e]     = pkh2(yacc[n][0] * rv0, yacc[n][1] * rv0);
            yf[kk][e + 1] = pkh2(yacc[n][2] * rv1, yacc[n][3] * rv1);
        }
    }

    // ---- WY = W_w @ Y + W_b : stage FULL 256-row W once ----
    __syncthreads();
    for (int i = t; i < 4096; i += 256) {
        int r = i >> 4, c16 = i & 15;
        *(uint4*)(smem + SM_WB + (uint32_t)(r * SQ + c16 * 16)) =
            *(const uint4*)(g_Whalf + (size_t)r * CI + c16 * 8);
    }
    __syncthreads();

    const uint32_t bW = sb + SM_WB + (uint32_t)(bn * SQ + bk);
    float* WYb = g_WY + (size_t)b * CIN * NPOS + q0;

    #pragma unroll 1
    for (int h = 0; h < 2; h++) {
        const uint32_t bWh_ = bW + (uint32_t)(h * 128 * SQ);
        float wacc[16][4];
        #pragma unroll
        for (int n = 0; n < 16; n++)
            #pragma unroll
            for (int j = 0; j < 4; j++) wacc[n][j] = 0.f;

        #pragma unroll
        for (int kk = 0; kk < 8; kk++) {
            #pragma unroll
            for (int np = 0; np < 8; np++) {
                uint32_t bh[4];
                ldsm4(bh, bWh_ + np * (16 * SQ) + kk * 32);
                mma16816h(wacc[2 * np],     yf[kk], bh[0], bh[1]);
                mma16816h(wacc[2 * np + 1], yf[kk], bh[2], bh[3]);
            }
        }

        #pragma unroll
        for (int n = 0; n < 16; n++) {
            int o = h * 128 + 8 * n + 2 * tc;
            float b0 = __ldg(&W_b[o]);
            float b1 = __ldg(&W_b[o + 1]);
            int r0 = 16 * w + g;
            WYb[(size_t)o * NPOS + r0]           = wacc[n][0] + b0;
            WYb[(size_t)(o + 1) * NPOS + r0]     = wacc[n][1] + b1;
            WYb[(size_t)o * NPOS + r0 + 8]       = wacc[n][2] + b0;
            WYb[(size_t)(o + 1) * NPOS + r0 + 8] = wacc[n][3] + b1;
        }
    }
}

// =================================================================
// K3: BN statistics — partial pass + finalize
// =================================================================
__global__ __launch_bounds__(256) void stats_part_kernel()
{
    const int c = blockIdx.x;
    const int s = blockIdx.y;
    const int t = threadIdx.x;
    float sm = 0.f, ss = 0.f;
    for (int b = 2 * s; b < 2 * s + 2; b++) {
        const float* p = g_WY + ((size_t)b * CIN + c) * NPOS;
        for (int i = t; i < NPOS / 4; i += 256) {
            float4 v = *(const float4*)&p[4 * i];
            sm += v.x + v.y + v.z + v.w;
            ss += v.x * v.x + v.y * v.y + v.z * v.z + v.w * v.w;
        }
    }
    __shared__ float rs[256], rss[256];
    rs[t] = sm; rss[t] = ss;
    __syncthreads();
    for (int o = 128; o > 0; o >>= 1) {
        if (t < o) { rs[t] += rs[t + o]; rss[t] += rss[t + o]; }
        __syncthreads();
    }
    if (t == 0) {
        g_ps[s * CIN + c]  = rs[0];
        g_pss[s * CIN + c] = rss[0];
    }
}

__global__ __launch_bounds__(256) void stats_fin_kernel()
{
    const int c = threadIdx.x;
    float sm = g_ps[c] + g_ps[CIN + c] + g_ps[2 * CIN + c] + g_ps[3 * CIN + c];
    float ss = g_pss[c] + g_pss[CIN + c] + g_pss[2 * CIN + c] + g_pss[3 * CIN + c];
    const float inv = 1.f / (float)(BATCH * NPOS);
    float mean = sm * inv;
    float var  = ss * inv - mean * mean;
    g_mean[c] = mean;
    g_rstd[c] = rsqrtf(var + 1e-5f);
}

// =================================================================
// K4: z = (wy - mean)*rstd*gamma + beta + x
// =================================================================
__global__ __launch_bounds__(256) void final_kernel(
    const float* __restrict__ x,
    const float* __restrict__ gamma, const float* __restrict__ beta,
    float* __restrict__ z)
{
    size_t i4 = (size_t)blockIdx.x * 256 + threadIdx.x;
    size_t i  = i4 * 4;
    int c = (int)((i >> 12) & 255);
    float m = g_mean[c], r = g_rstd[c], ga = gamma[c], be = beta[c];
    float4 wy = *(const float4*)&g_WY[i];
    float4 xv = *(const float4*)&x[i];
    float4 o;
    o.x = (wy.x - m) * r * ga + be + xv.x;
    o.y = (wy.y - m) * r * ga + be + xv.y;
    o.z = (wy.z - m) * r * ga + be + xv.z;
    o.w = (wy.w - m) * r * ga + be + xv.w;
    *(float4*)&z[i] = o;
}

// =================================================================
extern "C" void kernel_launch(void* const* d_in, const int* in_sizes, int n_in,
                              void* d_out, int out_size)
{
    const float* x       = (const float*)d_in[0];
    const float* g_w     = (const float*)d_in[1];
    const float* g_b     = (const float*)d_in[2];
    const float* theta_w = (const float*)d_in[3];
    const float* theta_b = (const float*)d_in[4];
    const float* phi_w   = (const float*)d_in[5];
    const float* phi_b   = (const float*)d_in[6];
    const float* W_w     = (const float*)d_in[7];
    const float* W_b     = (const float*)d_in[8];
    const float* bn_g    = (const float*)d_in[9];
    const float* bn_b    = (const float*)d_in[10];
    float* z = (float*)d_out;

    cudaFuncSetAttribute(proj_all_kernel, cudaFuncAttributeMaxDynamicSharedMemorySize, PA_SMEM);
    cudaFuncSetAttribute(attn_mma_kernel, cudaFuncAttributeMaxDynamicSharedMemorySize, SMEM_BYTES);

    split_wts_kernel<<<512, 256>>>(theta_w, phi_w, g_w, W_w);
    proj_all_kernel<<<dim3(32, 8, 3), 256, PA_SMEM>>>(x, theta_b, phi_b, g_b);
    attn_mma_kernel<<<dim3(32, 8), 256, SMEM_BYTES>>>(W_b);
    stats_part_kernel<<<dim3(256, 4), 256>>>();
    stats_fin_kernel<<<1, 256>>>();
    final_kernel<<<8192, 256>>>(x, bn_g, bn_b, z);
}

// round 16
// speedup vs baseline: 1.0209x; 1.0053x over previous
#include <cuda_runtime.h>
#include <cuda_bf16.h>
#include <cuda_fp16.h>
#include <math.h>
#include <stdint.h>

#define BATCH 8
#define CIN   256
#define CI    128
#define NPOS  4096

// ---------------- scratch (allocation-free: __device__ globals) ----------------
__device__ __align__(16) __nv_bfloat16 g_THh[(size_t)BATCH * NPOS * CI];
__device__ __align__(16) __nv_bfloat16 g_THl[(size_t)BATCH * NPOS * CI];
__device__ __align__(16) __nv_bfloat16 g_PHh[(size_t)BATCH * NPOS * CI];
__device__ __align__(16) __nv_bfloat16 g_PHl[(size_t)BATCH * NPOS * CI];
__device__ __align__(16) __half        g_G  [(size_t)BATCH * CI * NPOS];
__device__ __align__(16) __nv_bfloat16 g_WQh[2 * CI * CIN];
__device__ __align__(16) __nv_bfloat16 g_WQl[2 * CI * CIN];
__device__ __align__(16) __nv_bfloat16 g_WGh[CI * CIN];
__device__ __align__(16) __nv_bfloat16 g_WGl[CI * CIN];
__device__ __align__(16) __half        g_Whalf[CIN * CI];
__device__ float g_WY[(size_t)BATCH * CIN * NPOS];
__device__ float g_ps[4 * CIN], g_pss[4 * CIN];
__device__ float g_mean[CIN];
__device__ float g_rstd[CIN];

// ---------------- helpers ----------------
__device__ __forceinline__ uint32_t s2u(const void* p) {
    uint32_t a;
    asm("{ .reg .u64 t; cvta.to.shared.u64 t, %1; cvt.u32.u64 %0, t; }" : "=r"(a) : "l"(p));
    return a;
}
__device__ __forceinline__ void ldsm4(uint32_t r[4], uint32_t addr) {
    asm volatile("ldmatrix.sync.aligned.m8n8.x4.shared.b16 {%0,%1,%2,%3}, [%4];"
                 : "=r"(r[0]), "=r"(r[1]), "=r"(r[2]), "=r"(r[3]) : "r"(addr));
}
__device__ __forceinline__ void ldsm4t(uint32_t r[4], uint32_t addr) {
    asm volatile("ldmatrix.sync.aligned.m8n8.x4.trans.shared.b16 {%0,%1,%2,%3}, [%4];"
                 : "=r"(r[0]), "=r"(r[1]), "=r"(r[2]), "=r"(r[3]) : "r"(addr));
}
__device__ __forceinline__ void mma16816(float d[4], const uint32_t a[4],
                                         uint32_t b0, uint32_t b1) {
    asm volatile(
        "mma.sync.aligned.m16n8k16.row.col.f32.bf16.bf16.f32 "
        "{%0,%1,%2,%3}, {%4,%5,%6,%7}, {%8,%9}, {%0,%1,%2,%3};"
        : "+f"(d[0]), "+f"(d[1]), "+f"(d[2]), "+f"(d[3])
        : "r"(a[0]), "r"(a[1]), "r"(a[2]), "r"(a[3]), "r"(b0), "r"(b1));
}
__device__ __forceinline__ void mma16816h(float d[4], const uint32_t a[4],
                                          uint32_t b0, uint32_t b1) {
    asm volatile(
        "mma.sync.aligned.m16n8k16.row.col.f32.f16.f16.f32 "
        "{%0,%1,%2,%3}, {%4,%5,%6,%7}, {%8,%9}, {%0,%1,%2,%3};"
        : "+f"(d[0]), "+f"(d[1]), "+f"(d[2]), "+f"(d[3])
        : "r"(a[0]), "r"(a[1]), "r"(a[2]), "r"(a[3]), "r"(b0), "r"(b1));
}
__device__ __forceinline__ void cpa16(uint32_t dst, const void* src) {
    asm volatile("cp.async.cg.shared.global [%0], [%1], 16;" :: "r"(dst), "l"(src));
}
#define CP_COMMIT() asm volatile("cp.async.commit_group;" ::: "memory")
#define CP_WAIT0()  asm volatile("cp.async.wait_group 0;" ::: "memory")
#define CP_WAIT1()  asm volatile("cp.async.wait_group 1;" ::: "memory")

__device__ __forceinline__ uint32_t pkbf(float a, float b, float* ra, float* rb) {
    __nv_bfloat162 h2 = __floats2bfloat162_rn(a, b);
    uint32_t u = *reinterpret_cast<uint32_t*>(&h2);
    *ra = a - __uint_as_float(u << 16);
    *rb = b - __uint_as_float(u & 0xffff0000u);
    return u;
}
__device__ __forceinline__ uint32_t pkbf2(float a, float b) {
    __nv_bfloat162 h2 = __floats2bfloat162_rn(a, b);
    return *reinterpret_cast<uint32_t*>(&h2);
}
__device__ __forceinline__ uint32_t pkh2(float a, float b) {
    __half2 h2 = __floats2half2_rn(a, b);
    return *reinterpret_cast<uint32_t*>(&h2);
}

// =================================================================
// K0: split WEIGHTS only
// =================================================================
__global__ __launch_bounds__(256) void split_wts_kernel(
    const float* __restrict__ thw, const float* __restrict__ phw,
    const float* __restrict__ gw,  const float* __restrict__ Ww)
{
    int i = blockIdx.x * 256 + threadIdx.x;
    int which = i >> 15, j = i & 32767;
    if (which == 3) { g_Whalf[j] = __float2half(Ww[j]); return; }
    float v;
    __nv_bfloat16 *dh, *dl;
    int o;
    if (which == 0)      { v = thw[j]; dh = g_WQh; dl = g_WQl; o = j; }
    else if (which == 1) { v = phw[j]; dh = g_WQh; dl = g_WQl; o = 32768 + j; }
    else                 { v = gw[j];  dh = g_WGh; dl = g_WGl; o = j; }
    __nv_bfloat16 h = __float2bfloat16(v);
    dh[o] = h;
    dl[o] = __float2bfloat16(v - __bfloat162float(h));
}

// =================================================================
// K1: ALL projections fused (z: 0 theta, 1 phi, 2 g). x converted in-kernel.
// =================================================================
#define PSQ 272
#define PSW 80
#define PA_XH 0
#define PA_XL 8704
#define PA_WH 17408
#define PA_WL 27648
#define PA_BUF 37888
#define PA_BIAS 75776
#define PA_SMEM 76800

__device__ __forceinline__ void cvt_sts_x(char* smem, uint32_t bufbase, int t,
                                          const float4 xr[4])
{
    const float* f = (const float*)xr;
    uint32_t h[8], l[8];
    #pragma unroll
    for (int p = 0; p < 8; p++) {
        float r0, r1;
        h[p] = pkbf(f[2 * p], f[2 * p + 1], &r0, &r1);
        l[p] = pkbf2(r0, r1);
    }
    uint32_t off = (uint32_t)((t >> 3) * PSQ + (t & 7) * 32);
    *(uint4*)(smem + bufbase + PA_XH + off)      = make_uint4(h[0], h[1], h[2], h[3]);
    *(uint4*)(smem + bufbase + PA_XH + off + 16) = make_uint4(h[4], h[5], h[6], h[7]);
    *(uint4*)(smem + bufbase + PA_XL + off)      = make_uint4(l[0], l[1], l[2], l[3]);
    *(uint4*)(smem + bufbase + PA_XL + off + 16) = make_uint4(l[4], l[5], l[6], l[7]);
}

__global__ __launch_bounds__(256, 2) void proj_all_kernel(
    const float* __restrict__ x,
    const float* __restrict__ th_b, const float* __restrict__ ph_b,
    const float* __restrict__ g_b)
{
    extern __shared__ __align__(16) char smem[];
    const uint32_t sb = s2u(smem);
    const int t = threadIdx.x, w = t >> 5, L = t & 31;
    const int g = L >> 2, tc = L & 3;
    const int b = blockIdx.y;
    const int n0 = blockIdx.x * 128;
    const int z = blockIdx.z;

    float* bias = (float*)(smem + PA_BIAS);
    if (t < 128) bias[t] = (z == 0) ? th_b[t] : (z == 1) ? ph_b[t] : g_b[t];

    const float* xf = x + (size_t)b * CIN * NPOS + n0;
    const __nv_bfloat16* wh = (z < 2) ? (g_WQh + (size_t)z * 32768) : g_WGh;
    const __nv_bfloat16* wl = (z < 2) ? (g_WQl + (size_t)z * 32768) : g_WGl;

    const int xrow = t >> 3;
    const int xcol = (t & 7) * 16;

    float acc[16][4];
    #pragma unroll
    for (int j = 0; j < 16; j++)
        #pragma unroll
        for (int k = 0; k < 4; k++) acc[j][k] = 0.f;

    float4 xr[4];
    #pragma unroll
    for (int j = 0; j < 4; j++)
        xr[j] = *(const float4*)&xf[(size_t)xrow * NPOS + xcol + 4 * j];
    cvt_sts_x(smem, 0, t, xr);
    #pragma unroll
    for (int j = 0; j < 4; j++)
        xr[j] = *(const float4*)&xf[(size_t)(32 + xrow) * NPOS + xcol + 4 * j];
    for (int i = t; i < 512; i += 256) {
        int r = i >> 2, c4 = i & 3;
        uint32_t doff = (uint32_t)(r * PSW + c4 * 16);
        cpa16(sb + PA_WH + doff, wh + (size_t)r * CIN + c4 * 8);
        cpa16(sb + PA_WL + doff, wl + (size_t)r * CIN + c4 * 8);
    }
    CP_COMMIT();

    const uint32_t aoffN = (uint32_t)(((L & 7) + ((L >> 4) & 1) * 8) * PSQ + 32 * w +
                                      ((L >> 3) & 1) * 16);
    const uint32_t boffN = (uint32_t)(((L >> 4) * 8 + (L & 7)) * PSW + ((L >> 3) & 1) * 16);
    const uint32_t aoffG = (uint32_t)((16 * w + (L & 7) + ((L >> 3) & 1) * 8) * PSW +
                                      (L >> 4) * 16);
    const uint32_t boffG = (uint32_t)(((L & 7) + ((L >> 3) & 1) * 8) * PSQ + (L >> 4) * 16);

    #pragma unroll 1
    for (int ch = 0; ch < 8; ch++) {
        if (ch < 7) {
            int c0 = (ch + 1) * 32;
            uint32_t base = sb + ((ch + 1) & 1) * PA_BUF;
            for (int i = t; i < 512; i += 256) {
                int r = i >> 2, c4 = i & 3;
                uint32_t doff = (uint32_t)(r * PSW + c4 * 16);
                cpa16(base + PA_WH + doff, wh + (size_t)r * CIN + c0 + c4 * 8);
                cpa16(base + PA_WL + doff, wl + (size_t)r * CIN + c0 + c4 * 8);
            }
            CP_COMMIT();
            CP_WAIT1();
        } else {
            CP_WAIT0();
        }
        __syncthreads();

        if (ch < 7) {
            cvt_sts_x(smem, (uint32_t)(((ch + 1) & 1) * PA_BUF), t, xr);
            if (ch < 6) {
                const size_t rbase = (size_t)((ch + 2) * 32 + xrow) * NPOS + xcol;
                #pragma unroll
                for (int j = 0; j < 4; j++)
                    xr[j] = *(const float4*)&xf[rbase + 4 * j];
            }
        }

        const uint32_t xbase = sb + (ch & 1) * PA_BUF;
        if (z < 2) {
            const uint32_t aB = xbase + PA_XH + aoffN;
            const uint32_t bB = xbase + PA_WH + boffN;
            #pragma unroll
            for (int kk = 0; kk < 2; kk++) {
                uint32_t ah[4], al[4];
                ldsm4t(ah, aB + kk * 16 * PSQ);
                ldsm4t(al, aB + 8704 + kk * 16 * PSQ);
                #pragma unroll
                for (int np = 0; np < 8; np++) {
                    uint32_t bh[4], bl[4];
                    ldsm4(bh, bB + np * (16 * PSW) + kk * 32);
                    ldsm4(bl, bB + 10240 + np * (16 * PSW) + kk * 32);
                    mma16816(acc[2 * np],     ah, bh[0], bh[1]);
                    mma16816(acc[2 * np + 1], ah, bh[2], bh[3]);
                    mma16816(acc[2 * np],     ah, bl[0], bl[1]);
                    mma16816(acc[2 * np + 1], ah, bl[2], bl[3]);
                    mma16816(acc[2 * np],     al, bh[0], bh[1]);
                    mma16816(acc[2 * np + 1], al, bh[2], bh[3]);
                }
            }
        } else {
            const uint32_t aB = xbase + PA_WH + aoffG;
            const uint32_t bB = xbase + PA_XH + boffG;
            #pragma unroll
            for (int kk = 0; kk < 2; kk++) {
                uint32_t ah[4], al[4];
                ldsm4(ah, aB + kk * 32);
                ldsm4(al, aB + 10240 + kk * 32);
                #pragma unroll
                for (int np = 0; np < 8; np++) {
                    uint32_t bh[4], bl[4];
                    ldsm4t(bh, bB + np * 32 + kk * 16 * PSQ);
                    ldsm4t(bl, bB + 8704 + np * 32 + kk * 16 * PSQ);
                    mma16816(acc[2 * np],     ah, bh[0], bh[1]);
                    mma16816(acc[2 * np + 1], ah, bh[2], bh[3]);
                    mma16816(acc[2 * np],     ah, bl[0], bl[1]);
                    mma16816(acc[2 * np + 1], ah, bl[2], bl[3]);
                    mma16816(acc[2 * np],     al, bh[0], bh[1]);
                    mma16816(acc[2 * np + 1], al, bh[2], bh[3]);
                }
            }
        }
        __syncthreads();
    }

    if (z < 2) {
        const int nrow = n0 + 16 * w + g;
        const size_t rb0 = ((size_t)b * NPOS + nrow) * CI;
        const size_t rb1 = rb0 + (size_t)8 * CI;
        __nv_bfloat16* dh = z ? g_PHh : g_THh;
        __nv_bfloat16* dl = z ? g_PHl : g_THl;
        #pragma unroll
        for (int j = 0; j < 16; j++) {
            int o = 8 * j + 2 * tc;
            float b0 = bias[o], b1 = bias[o + 1];
            float r0, r1;
            uint32_t hp = pkbf(acc[j][0] + b0, acc[j][1] + b1, &r0, &r1);
            uint32_t lp = pkbf2(r0, r1);
            *(uint32_t*)(dh + rb0 + o) = hp;
            *(uint32_t*)(dl + rb0 + o) = lp;
            hp = pkbf(acc[j][2] + b0, acc[j][3] + b1, &r0, &r1);
            lp = pkbf2(r0, r1);
            *(uint32_t*)(dh + rb1 + o) = hp;
            *(uint32_t*)(dl + rb1 + o) = lp;
        }
    } else {
        const int o = 16 * w + g;
        const float b0 = bias[o], b8 = bias[o + 8];
        #pragma unroll
        for (int j = 0; j < 16; j++) {
            int n = 16 * (j >> 1) + 8 * (j & 1) + 2 * tc;
            size_t a0 = ((size_t)b * CI + o) * NPOS + n0 + n;
            size_t a8 = a0 + (size_t)8 * NPOS;
            *(uint32_t*)(g_G + a0) = pkh2(acc[j][0] + b0, acc[j][1] + b0);
            *(uint32_t*)(g_G + a8) = pkh2(acc[j][2] + b8, acc[j][3] + b8);
        }
    }
}

// =================================================================
// K2: attention — 128 threads / 64 queries per CTA, OCCUPANCY 2.
// Q staged in G region -> registers; steady smem = K dbl + G dbl = 106.5 KB.
// QK bf16 3-term, PV fp16 flash, W-conv fp16 full-W (aliases K region).
// =================================================================
#define SQ   272
#define SPG  144
#define SM_K0   0            // K buf: hi @0, lo @+17408 (34816/buf)
#define SM_K1   34816
#define SM_G0   69632        // G buf (18432/buf)
#define SM_G1   88064
#define SM_QSTG 69632        // Q staging aliases G region (hi @0, lo @+17408)
#define SMEM_BYTES 106496
#define SM_WB   0            // epilogue: full 256-row W tile aliases K0+K1

__global__ __launch_bounds__(128, 2) void attn_mma_kernel(const float* __restrict__ W_b)
{
    extern __shared__ __align__(16) char smem[];
    const uint32_t sb = s2u(smem);
    const int t = threadIdx.x, w = t >> 5, L = t & 31;
    const int b = blockIdx.y;
    const int q0 = blockIdx.x * 64;
    const int g  = L >> 2, tc = L & 3;

    const __nv_bfloat16* qh  = g_THh + ((size_t)b * NPOS + q0) * CI;
    const __nv_bfloat16* ql  = g_THl + ((size_t)b * NPOS + q0) * CI;
    const __nv_bfloat16* khb = g_PHh + (size_t)b * NPOS * CI;
    const __nv_bfloat16* klb = g_PHl + (size_t)b * NPOS * CI;
    const __half*        ghb = g_G + (size_t)b * CI * NPOS;

    // prologue group 1: Q -> staging (G region), K(0) -> K0
    for (int i = t; i < 1024; i += 128) {           // Q: 64 rows x 16 chunks
        int r = i >> 4, c16 = i & 15;
        uint32_t doff = (uint32_t)(r * SQ + c16 * 16);
        cpa16(sb + SM_QSTG + doff, qh + (size_t)r * CI + c16 * 8);
        cpa16(sb + SM_QSTG + 17408 + doff, ql + (size_t)r * CI + c16 * 8);
    }
    for (int i = t; i < 1024; i += 128) {           // K(0): 64 rows x 16 chunks
        int r = i >> 4, c16 = i & 15;
        uint32_t doff = (uint32_t)(r * SQ + c16 * 16);
        cpa16(sb + SM_K0 + doff, khb + (size_t)r * CI + c16 * 8);
        cpa16(sb + SM_K0 + 17408 + doff, klb + (size_t)r * CI + c16 * 8);
    }
    CP_COMMIT();

    const int lr = ((L >> 3) & 1) * 8 + (L & 7);
    const int lk = (L >> 4) * 16;
    const int bn = (L >> 4) * 8 + (L & 7);
    const int bk = ((L >> 3) & 1) * 16;

    const uint32_t kOff = (uint32_t)(bn * SQ + bk);
    const uint32_t gOff = (uint32_t)(bn * SPG + bk);

    // hoist Q fragments from staging, then release staging for G
    CP_WAIT0();
    __syncthreads();
    uint32_t qfh[8][4], qfl[8][4];
    {
        const uint32_t aQ = sb + SM_QSTG + (uint32_t)((16 * w + lr) * SQ + lk);
        #pragma unroll
        for (int kk = 0; kk < 8; kk++) {
            ldsm4(qfh[kk], aQ + kk * 32);
            ldsm4(qfl[kk], aQ + 17408 + kk * 32);
        }
    }
    __syncthreads();   // all warps done reading staging

    // prologue group 2: G(0) -> G0
    for (int i = t; i < 1024; i += 128) {
        int r = i >> 3, c8 = i & 7;
        cpa16(sb + SM_G0 + (uint32_t)(r * SPG + c8 * 16), ghb + (size_t)r * NPOS + c8 * 8);
    }
    CP_COMMIT();

    float yacc[16][4];
    #pragma unroll
    for (int n = 0; n < 16; n++)
        #pragma unroll
        for (int j = 0; j < 4; j++) yacc[n][j] = 0.f;
    float ls0 = 0.f, ls1 = 0.f;
    float m0 = -INFINITY, m1 = -INFINITY;

    #pragma unroll 1
    for (int mt = 0; mt < NPOS / 64; mt++) {
        CP_WAIT0();
        __syncthreads();   // K(mt), G(mt) ready; prev-buffer readers done

        if (mt < 63) {
            const int m1i = mt * 64 + 64;
            const uint32_t kdst = sb + (((mt + 1) & 1) ? SM_K1 : SM_K0);
            const uint32_t gdst = sb + (((mt + 1) & 1) ? SM_G1 : SM_G0);
            for (int i = t; i < 1024; i += 128) {
                int r = i >> 4, c16 = i & 15;
                uint32_t doff = (uint32_t)(r * SQ + c16 * 16);
                cpa16(kdst + doff, khb + (size_t)(m1i + r) * CI + c16 * 8);
                cpa16(kdst + 17408 + doff, klb + (size_t)(m1i + r) * CI + c16 * 8);
            }
            for (int i = t; i < 1024; i += 128) {
                int r = i >> 3, c8 = i & 7;
                cpa16(gdst + (uint32_t)(r * SPG + c8 * 16),
                      ghb + (size_t)r * NPOS + m1i + c8 * 8);
            }
            CP_COMMIT();
        }

        // ---- QK: bf16 3-term, Q frags resident ----
        const uint32_t bKh = sb + ((mt & 1) ? SM_K1 : SM_K0) + kOff;
        const uint32_t bKl = bKh + 17408;
        float acc[8][4];
        #pragma unroll
        for (int n = 0; n < 8; n++)
            #pragma unroll
            for (int j = 0; j < 4; j++) acc[n][j] = 0.f;
        #pragma unroll
        for (int kk = 0; kk < 8; kk++) {
            #pragma unroll
            for (int np = 0; np < 4; np++) {
                uint32_t bh[4], bl[4];
                ldsm4(bh, bKh + np * (16 * SQ) + kk * 32);
                ldsm4(bl, bKl + np * (16 * SQ) + kk * 32);
                mma16816(acc[2 * np],     qfh[kk], bh[0], bh[1]);
                mma16816(acc[2 * np + 1], qfh[kk], bh[2], bh[3]);
                mma16816(acc[2 * np],     qfh[kk], bl[0], bl[1]);
                mma16816(acc[2 * np + 1], qfh[kk], bl[2], bl[3]);
                mma16816(acc[2 * np],     qfl[kk], bh[0], bh[1]);
                mma16816(acc[2 * np + 1], qfl[kk], bh[2], bh[3]);
            }
        }

        // ---- flash online-max softmax (skip-rescale vote) ----
        float tm0 = -INFINITY, tm1 = -INFINITY;
        #pragma unroll
        for (int n = 0; n < 8; n++) {
            tm0 = fmaxf(tm0, fmaxf(acc[n][0], acc[n][1]));
            tm1 = fmaxf(tm1, fmaxf(acc[n][2], acc[n][3]));
        }
        tm0 = fmaxf(tm0, __shfl_xor_sync(0xffffffffu, tm0, 1));
        tm0 = fmaxf(tm0, __shfl_xor_sync(0xffffffffu, tm0, 2));
        tm1 = fmaxf(tm1, __shfl_xor_sync(0xffffffffu, tm1, 1));
        tm1 = fmaxf(tm1, __shfl_xor_sync(0xffffffffu, tm1, 2));
        bool noup = (tm0 <= m0) && (tm1 <= m1);
        if (!__all_sync(0xffffffffu, noup)) {
            float mn0 = fmaxf(m0, tm0), mn1 = fmaxf(m1, tm1);
            float al0 = __expf(m0 - mn0), al1 = __expf(m1 - mn1);
            m0 = mn0; m1 = mn1;
            ls0 *= al0; ls1 *= al1;
            #pragma unroll
            for (int n = 0; n < 16; n++) {
                yacc[n][0] *= al0; yacc[n][1] *= al0;
                yacc[n][2] *= al1; yacc[n][3] *= al1;
            }
        }

        uint32_t pf[4][4];
        #pragma unroll
        for (int n = 0; n < 8; n++) {
            float p0 = __expf(acc[n][0] - m0);
            float p1 = __expf(acc[n][1] - m0);
            float p2 = __expf(acc[n][2] - m1);
            float p3 = __expf(acc[n][3] - m1);
            ls0 += p0 + p1;
            ls1 += p2 + p3;
            int kk = n >> 1, e = (n & 1) * 2;
            pf[kk][e]     = pkh2(p0, p1);
            pf[kk][e + 1] = pkh2(p2, p3);
        }

        // ---- PV (fp16 single term) ----
        const uint32_t bG = sb + ((mt & 1) ? SM_G1 : SM_G0) + gOff;
        #pragma unroll
        for (int kk = 0; kk < 4; kk++) {
            #pragma unroll
            for (int np = 0; np < 8; np++) {
                uint32_t bh[4];
                ldsm4(bh, bG + np * (16 * SPG) + kk * 32);
                mma16816h(yacc[2 * np],     pf[kk], bh[0], bh[1]);
                mma16816h(yacc[2 * np + 1], pf[kk], bh[2], bh[3]);
            }
        }
    }

    // ---- finalize row sums ----
    ls0 += __shfl_xor_sync(0xffffffffu, ls0, 1);
    ls0 += __shfl_xor_sync(0xffffffffu, ls0, 2);
    ls1 += __shfl_xor_sync(0xffffffffu, ls1, 1);
    ls1 += __shfl_xor_sync(0xffffffffu, ls1, 2);

    uint32_t yf[8][4];
    {
        float rv0 = 1.f / ls0, rv1 = 1.f / ls1;
        #pragma unroll
        for (int n = 0; n < 16; n++) {
            int kk = n >> 1, e = (n & 1) * 2;
            yf[kk][e]     = pkh2(yacc[n][0] * rv0, yacc[n][1] * rv0);
            yf[kk][e + 1] = pkh2(yacc[n][2] * rv1, yacc[n][3] * rv1);
        }
    }

    // ---- WY = W_w @ Y + W_b : stage FULL 256-row W once (aliases K0+K1) ----
    __syncthreads();
    for (int i = t; i < 4096; i += 128) {
        int r = i >> 4, c16 = i & 15;
        *(uint4*)(smem + SM_WB + (uint32_t)(r * SQ + c16 * 16)) =
            *(const uint4*)(g_Whalf + (size_t)r * CI + c16 * 8);
    }
    __syncthreads();

    const uint32_t bW = sb + SM_WB + (uint32_t)(bn * SQ + bk);
    float* WYb = g_WY + (size_t)b * CIN * NPOS + q0;

    #pragma unroll 1
    for (int h = 0; h < 2; h++) {
        const uint32_t bWh_ = bW + (uint32_t)(h * 128 * SQ);
        float wacc[16][4];
        #pragma unroll
        for (int n = 0; n < 16; n++)
            #pragma unroll
            for (int j = 0; j < 4; j++) wacc[n][j] = 0.f;

        #pragma unroll
        for (int kk = 0; kk < 8; kk++) {
            #pragma unroll
            for (int np = 0; np < 8; np++) {
                uint32_t bh[4];
                ldsm4(bh, bWh_ + np * (16 * SQ) + kk * 32);
                mma16816h(wacc[2 * np],     yf[kk], bh[0], bh[1]);
                mma16816h(wacc[2 * np + 1], yf[kk], bh[2], bh[3]);
            }
        }

        #pragma unroll
        for (int n = 0; n < 16; n++) {
            int o = h * 128 + 8 * n + 2 * tc;
            float b0 = __ldg(&W_b[o]);
            float b1 = __ldg(&W_b[o + 1]);
            int r0 = 16 * w + g;
            WYb[(size_t)o * NPOS + r0]           = wacc[n][0] + b0;
            WYb[(size_t)(o + 1) * NPOS + r0]     = wacc[n][1] + b1;
            WYb[(size_t)o * NPOS + r0 + 8]       = wacc[n][2] + b0;
            WYb[(size_t)(o + 1) * NPOS + r0 + 8] = wacc[n][3] + b1;
        }
    }
}

// =================================================================
// K3: BN statistics — partial pass + finalize
// =================================================================
__global__ __launch_bounds__(256) void stats_part_kernel()
{
    const int c = blockIdx.x;
    const int s = blockIdx.y;
    const int t = threadIdx.x;
    float sm = 0.f, ss = 0.f;
    for (int b = 2 * s; b < 2 * s + 2; b++) {
        const float* p = g_WY + ((size_t)b * CIN + c) * NPOS;
        for (int i = t; i < NPOS / 4; i += 256) {
            float4 v = *(const float4*)&p[4 * i];
            sm += v.x + v.y + v.z + v.w;
            ss += v.x * v.x + v.y * v.y + v.z * v.z + v.w * v.w;
        }
    }
    __shared__ float rs[256], rss[256];
    rs[t] = sm; rss[t] = ss;
    __syncthreads();
    for (int o = 128; o > 0; o >>= 1) {
        if (t < o) { rs[t] += rs[t + o]; rss[t] += rss[t + o]; }
        __syncthreads();
    }
    if (t == 0) {
        g_ps[s * CIN + c]  = rs[0];
        g_pss[s * CIN + c] = rss[0];
    }
}

__global__ __launch_bounds__(256) void stats_fin_kernel()
{
    const int c = threadIdx.x;
    float sm = g_ps[c] + g_ps[CIN + c] + g_ps[2 * CIN + c] + g_ps[3 * CIN + c];
    float ss = g_pss[c] + g_pss[CIN + c] + g_pss[2 * CIN + c] + g_pss[3 * CIN + c];
    const float inv = 1.f / (float)(BATCH * NPOS);
    float mean = sm * inv;
    float var  = ss * inv - mean * mean;
    g_mean[c] = mean;
    g_rstd[c] = rsqrtf(var + 1e-5f);
}

// =================================================================
// K4: z = (wy - mean)*rstd*gamma + beta + x
// =================================================================
__global__ __launch_bounds__(256) void final_kernel(
    const float* __restrict__ x,
    const float* __restrict__ gamma, const float* __restrict__ beta,
    float* __restrict__ z)
{
    size_t i4 = (size_t)blockIdx.x * 256 + threadIdx.x;
    size_t i  = i4 * 4;
    int c = (int)((i >> 12) & 255);
    float m = g_mean[c], r = g_rstd[c], ga = gamma[c], be = beta[c];
    float4 wy = *(const float4*)&g_WY[i];
    float4 xv = *(const float4*)&x[i];
    float4 o;
    o.x = (wy.x - m) * r * ga + be + xv.x;
    o.y = (wy.y - m) * r * ga + be + xv.y;
    o.z = (wy.z - m) * r * ga + be + xv.z;
    o.w = (wy.w - m) * r * ga + be + xv.w;
    *(float4*)&z[i] = o;
}

// =================================================================
extern "C" void kernel_launch(void* const* d_in, const int* in_sizes, int n_in,
                              void* d_out, int out_size)
{
    const float* x       = (const float*)d_in[0];
    const float* g_w     = (const float*)d_in[1];
    const float* g_b     = (const float*)d_in[2];
    const float* theta_w = (const float*)d_in[3];
    const float* theta_b = (const float*)d_in[4];
    const float* phi_w   = (const float*)d_in[5];
    const float* phi_b   = (const float*)d_in[6];
    const float* W_w     = (const float*)d_in[7];
    const float* W_b     = (const float*)d_in[8];
    const float* bn_g    = (const float*)d_in[9];
    const float* bn_b    = (const float*)d_in[10];
    float* z = (float*)d_out;

    cudaFuncSetAttribute(proj_all_kernel, cudaFuncAttributeMaxDynamicSharedMemorySize, PA_SMEM);
    cudaFuncSetAttribute(attn_mma_kernel, cudaFuncAttributeMaxDynamicSharedMemorySize, SMEM_BYTES);

    split_wts_kernel<<<512, 256>>>(theta_w, phi_w, g_w, W_w);
    proj_all_kernel<<<dim3(32, 8, 3), 256, PA_SMEM>>>(x, theta_b, phi_b, g_b);
    attn_mma_kernel<<<dim3(64, 8), 128, SMEM_BYTES>>>(W_b);
    stats_part_kernel<<<dim3(256, 4), 256>>>();
    stats_fin_kernel<<<1, 256>>>();
    final_kernel<<<8192, 256>>>(x, bn_g, bn_b, z);
}

// round 17
// speedup vs baseline: 1.2911x; 1.2646x over previous
#include <cuda_runtime.h>
#include <cuda_bf16.h>
#include <cuda_fp16.h>
#include <math.h>
#include <stdint.h>

#define BATCH 8
#define CIN   256
#define CI    128
#define NPOS  4096

// ---------------- scratch (allocation-free: __device__ globals) ----------------
__device__ __align__(16) __half        g_THh[(size_t)BATCH * NPOS * CI];  // theta fp16 hi
__device__ __align__(16) __half        g_THl[(size_t)BATCH * NPOS * CI];  // theta fp16 lo
__device__ __align__(16) __half        g_PH [(size_t)BATCH * NPOS * CI];  // phi fp16 single
__device__ __align__(16) __half        g_G  [(size_t)BATCH * CI * NPOS];
__device__ __align__(16) __nv_bfloat16 g_WQh[2 * CI * CIN];
__device__ __align__(16) __nv_bfloat16 g_WQl[2 * CI * CIN];
__device__ __align__(16) __nv_bfloat16 g_WGh[CI * CIN];
__device__ __align__(16) __nv_bfloat16 g_WGl[CI * CIN];
__device__ __align__(16) __half        g_Whalf[CIN * CI];
__device__ float g_WY[(size_t)BATCH * CIN * NPOS];
__device__ float g_ps[4 * CIN], g_pss[4 * CIN];
__device__ float g_mean[CIN];
__device__ float g_rstd[CIN];

// ---------------- helpers ----------------
__device__ __forceinline__ uint32_t s2u(const void* p) {
    uint32_t a;
    asm("{ .reg .u64 t; cvta.to.shared.u64 t, %1; cvt.u32.u64 %0, t; }" : "=r"(a) : "l"(p));
    return a;
}
__device__ __forceinline__ void ldsm4(uint32_t r[4], uint32_t addr) {
    asm volatile("ldmatrix.sync.aligned.m8n8.x4.shared.b16 {%0,%1,%2,%3}, [%4];"
                 : "=r"(r[0]), "=r"(r[1]), "=r"(r[2]), "=r"(r[3]) : "r"(addr));
}
__device__ __forceinline__ void ldsm4t(uint32_t r[4], uint32_t addr) {
    asm volatile("ldmatrix.sync.aligned.m8n8.x4.trans.shared.b16 {%0,%1,%2,%3}, [%4];"
                 : "=r"(r[0]), "=r"(r[1]), "=r"(r[2]), "=r"(r[3]) : "r"(addr));
}
__device__ __forceinline__ void mma16816(float d[4], const uint32_t a[4],
                                         uint32_t b0, uint32_t b1) {
    asm volatile(
        "mma.sync.aligned.m16n8k16.row.col.f32.bf16.bf16.f32 "
        "{%0,%1,%2,%3}, {%4,%5,%6,%7}, {%8,%9}, {%0,%1,%2,%3};"
        : "+f"(d[0]), "+f"(d[1]), "+f"(d[2]), "+f"(d[3])
        : "r"(a[0]), "r"(a[1]), "r"(a[2]), "r"(a[3]), "r"(b0), "r"(b1));
}
__device__ __forceinline__ void mma16816h(float d[4], const uint32_t a[4],
                                          uint32_t b0, uint32_t b1) {
    asm volatile(
        "mma.sync.aligned.m16n8k16.row.col.f32.f16.f16.f32 "
        "{%0,%1,%2,%3}, {%4,%5,%6,%7}, {%8,%9}, {%0,%1,%2,%3};"
        : "+f"(d[0]), "+f"(d[1]), "+f"(d[2]), "+f"(d[3])
        : "r"(a[0]), "r"(a[1]), "r"(a[2]), "r"(a[3]), "r"(b0), "r"(b1));
}
__device__ __forceinline__ void cpa16(uint32_t dst, const void* src) {
    asm volatile("cp.async.cg.shared.global [%0], [%1], 16;" :: "r"(dst), "l"(src));
}
#define CP_COMMIT() asm volatile("cp.async.commit_group;" ::: "memory")
#define CP_WAIT0()  asm volatile("cp.async.wait_group 0;" ::: "memory")
#define CP_WAIT1()  asm volatile("cp.async.wait_group 1;" ::: "memory")

__device__ __forceinline__ uint32_t pkbf(float a, float b, float* ra, float* rb) {
    __nv_bfloat162 h2 = __floats2bfloat162_rn(a, b);
    uint32_t u = *reinterpret_cast<uint32_t*>(&h2);
    *ra = a - __uint_as_float(u << 16);
    *rb = b - __uint_as_float(u & 0xffff0000u);
    return u;
}
__device__ __forceinline__ uint32_t pkbf2(float a, float b) {
    __nv_bfloat162 h2 = __floats2bfloat162_rn(a, b);
    return *reinterpret_cast<uint32_t*>(&h2);
}
__device__ __forceinline__ uint32_t pkh2(float a, float b) {
    __half2 h2 = __floats2half2_rn(a, b);
    return *reinterpret_cast<uint32_t*>(&h2);
}
// fp16 2-term split: returns packed hi, residuals via ra/rb
__device__ __forceinline__ uint32_t pkh2r(float a, float b, float* ra, float* rb) {
    __half2 h2 = __floats2half2_rn(a, b);
    *ra = a - __low2float(h2);
    *rb = b - __high2float(h2);
    return *reinterpret_cast<uint32_t*>(&h2);
}

// =================================================================
// K0: split WEIGHTS only
// =================================================================
__global__ __launch_bounds__(256) void split_wts_kernel(
    const float* __restrict__ thw, const float* __restrict__ phw,
    const float* __restrict__ gw,  const float* __restrict__ Ww)
{
    int i = blockIdx.x * 256 + threadIdx.x;
    int which = i >> 15, j = i & 32767;
    if (which == 3) { g_Whalf[j] = __float2half(Ww[j]); return; }
    float v;
    __nv_bfloat16 *dh, *dl;
    int o;
    if (which == 0)      { v = thw[j]; dh = g_WQh; dl = g_WQl; o = j; }
    else if (which == 1) { v = phw[j]; dh = g_WQh; dl = g_WQl; o = 32768 + j; }
    else                 { v = gw[j];  dh = g_WGh; dl = g_WGl; o = j; }
    __nv_bfloat16 h = __float2bfloat16(v);
    dh[o] = h;
    dl[o] = __float2bfloat16(v - __bfloat162float(h));
}

// =================================================================
// K1: ALL projections fused (z: 0 theta, 1 phi, 2 g). x converted in-kernel.
// theta -> fp16 hi/lo, phi -> fp16 single, g -> fp16 single.
// =================================================================
#define PSQ 272
#define PSW 80
#define PA_XH 0
#define PA_XL 8704
#define PA_WH 17408
#define PA_WL 27648
#define PA_BUF 37888
#define PA_BIAS 75776
#define PA_SMEM 76800

__device__ __forceinline__ void cvt_sts_x(char* smem, uint32_t bufbase, int t,
                                          const float4 xr[4])
{
    const float* f = (const float*)xr;
    uint32_t h[8], l[8];
    #pragma unroll
    for (int p = 0; p < 8; p++) {
        float r0, r1;
        h[p] = pkbf(f[2 * p], f[2 * p + 1], &r0, &r1);
        l[p] = pkbf2(r0, r1);
    }
    uint32_t off = (uint32_t)((t >> 3) * PSQ + (t & 7) * 32);
    *(uint4*)(smem + bufbase + PA_XH + off)      = make_uint4(h[0], h[1], h[2], h[3]);
    *(uint4*)(smem + bufbase + PA_XH + off + 16) = make_uint4(h[4], h[5], h[6], h[7]);
    *(uint4*)(smem + bufbase + PA_XL + off)      = make_uint4(l[0], l[1], l[2], l[3]);
    *(uint4*)(smem + bufbase + PA_XL + off + 16) = make_uint4(l[4], l[5], l[6], l[7]);
}

__global__ __launch_bounds__(256, 2) void proj_all_kernel(
    const float* __restrict__ x,
    const float* __restrict__ th_b, const float* __restrict__ ph_b,
    const float* __restrict__ g_b)
{
    extern __shared__ __align__(16) char smem[];
    const uint32_t sb = s2u(smem);
    const int t = threadIdx.x, w = t >> 5, L = t & 31;
    const int g = L >> 2, tc = L & 3;
    const int b = blockIdx.y;
    const int n0 = blockIdx.x * 128;
    const int z = blockIdx.z;

    float* bias = (float*)(smem + PA_BIAS);
    if (t < 128) bias[t] = (z == 0) ? th_b[t] : (z == 1) ? ph_b[t] : g_b[t];

    const float* xf = x + (size_t)b * CIN * NPOS + n0;
    const __nv_bfloat16* wh = (z < 2) ? (g_WQh + (size_t)z * 32768) : g_WGh;
    const __nv_bfloat16* wl = (z < 2) ? (g_WQl + (size_t)z * 32768) : g_WGl;

    const int xrow = t >> 3;
    const int xcol = (t & 7) * 16;

    float acc[16][4];
    #pragma unroll
    for (int j = 0; j < 16; j++)
        #pragma unroll
        for (int k = 0; k < 4; k++) acc[j][k] = 0.f;

    float4 xr[4];
    #pragma unroll
    for (int j = 0; j < 4; j++)
        xr[j] = *(const float4*)&xf[(size_t)xrow * NPOS + xcol + 4 * j];
    cvt_sts_x(smem, 0, t, xr);
    #pragma unroll
    for (int j = 0; j < 4; j++)
        xr[j] = *(const float4*)&xf[(size_t)(32 + xrow) * NPOS + xcol + 4 * j];
    for (int i = t; i < 512; i += 256) {
        int r = i >> 2, c4 = i & 3;
        uint32_t doff = (uint32_t)(r * PSW + c4 * 16);
        cpa16(sb + PA_WH + doff, wh + (size_t)r * CIN + c4 * 8);
        cpa16(sb + PA_WL + doff, wl + (size_t)r * CIN + c4 * 8);
    }
    CP_COMMIT();

    const uint32_t aoffN = (uint32_t)(((L & 7) + ((L >> 4) & 1) * 8) * PSQ + 32 * w +
                                      ((L >> 3) & 1) * 16);
    const uint32_t boffN = (uint32_t)(((L >> 4) * 8 + (L & 7)) * PSW + ((L >> 3) & 1) * 16);
    const uint32_t aoffG = (uint32_t)((16 * w + (L & 7) + ((L >> 3) & 1) * 8) * PSW +
                                      (L >> 4) * 16);
    const uint32_t boffG = (uint32_t)(((L & 7) + ((L >> 3) & 1) * 8) * PSQ + (L >> 4) * 16);

    #pragma unroll 1
    for (int ch = 0; ch < 8; ch++) {
        if (ch < 7) {
            int c0 = (ch + 1) * 32;
            uint32_t base = sb + ((ch + 1) & 1) * PA_BUF;
            for (int i = t; i < 512; i += 256) {
                int r = i >> 2, c4 = i & 3;
                uint32_t doff = (uint32_t)(r * PSW + c4 * 16);
                cpa16(base + PA_WH + doff, wh + (size_t)r * CIN + c0 + c4 * 8);
                cpa16(base + PA_WL + doff, wl + (size_t)r * CIN + c0 + c4 * 8);
            }
            CP_COMMIT();
            CP_WAIT1();
        } else {
            CP_WAIT0();
        }
        __syncthreads();

        if (ch < 7) {
            cvt_sts_x(smem, (uint32_t)(((ch + 1) & 1) * PA_BUF), t, xr);
            if (ch < 6) {
                const size_t rbase = (size_t)((ch + 2) * 32 + xrow) * NPOS + xcol;
                #pragma unroll
                for (int j = 0; j < 4; j++)
                    xr[j] = *(const float4*)&xf[rbase + 4 * j];
            }
        }

        const uint32_t xbase = sb + (ch & 1) * PA_BUF;
        if (z < 2) {
            const uint32_t aB = xbase + PA_XH + aoffN;
            const uint32_t bB = xbase + PA_WH + boffN;
            #pragma unroll
            for (int kk = 0; kk < 2; kk++) {
                uint32_t ah[4], al[4];
                ldsm4t(ah, aB + kk * 16 * PSQ);
                ldsm4t(al, aB + 8704 + kk * 16 * PSQ);
                #pragma unroll
                for (int np = 0; np < 8; np++) {
                    uint32_t bh[4], bl[4];
                    ldsm4(bh, bB + np * (16 * PSW) + kk * 32);
                    ldsm4(bl, bB + 10240 + np * (16 * PSW) + kk * 32);
                    mma16816(acc[2 * np],     ah, bh[0], bh[1]);
                    mma16816(acc[2 * np + 1], ah, bh[2], bh[3]);
                    mma16816(acc[2 * np],     ah, bl[0], bl[1]);
                    mma16816(acc[2 * np + 1], ah, bl[2], bl[3]);
                    mma16816(acc[2 * np],     al, bh[0], bh[1]);
                    mma16816(acc[2 * np + 1], al, bh[2], bh[3]);
                }
            }
        } else {
            const uint32_t aB = xbase + PA_WH + aoffG;
            const uint32_t bB = xbase + PA_XH + boffG;
            #pragma unroll
            for (int kk = 0; kk < 2; kk++) {
                uint32_t ah[4], al[4];
                ldsm4(ah, aB + kk * 32);
                ldsm4(al, aB + 10240 + kk * 32);
                #pragma unroll
                for (int np = 0; np < 8; np++) {
                    uint32_t bh[4], bl[4];
                    ldsm4t(bh, bB + np * 32 + kk * 16 * PSQ);
                    ldsm4t(bl, bB + 8704 + np * 32 + kk * 16 * PSQ);
                    mma16816(acc[2 * np],     ah, bh[0], bh[1]);
                    mma16816(acc[2 * np + 1], ah, bh[2], bh[3]);
                    mma16816(acc[2 * np],     ah, bl[0], bl[1]);
                    mma16816(acc[2 * np + 1], ah, bl[2], bl[3]);
                    mma16816(acc[2 * np],     al, bh[0], bh[1]);
                    mma16816(acc[2 * np + 1], al, bh[2], bh[3]);
                }
            }
        }
        __syncthreads();
    }

    if (z == 0) {          // theta -> fp16 hi/lo
        const int nrow = n0 + 16 * w + g;
        const size_t rb0 = ((size_t)b * NPOS + nrow) * CI;
        const size_t rb1 = rb0 + (size_t)8 * CI;
        #pragma unroll
        for (int j = 0; j < 16; j++) {
            int o = 8 * j + 2 * tc;
            float b0 = bias[o], b1 = bias[o + 1];
            float r0, r1;
            uint32_t hp = pkh2r(acc[j][0] + b0, acc[j][1] + b1, &r0, &r1);
            *(uint32_t*)(g_THh + rb0 + o) = hp;
            *(uint32_t*)(g_THl + rb0 + o) = pkh2(r0, r1);
            hp = pkh2r(acc[j][2] + b0, acc[j][3] + b1, &r0, &r1);
            *(uint32_t*)(g_THh + rb1 + o) = hp;
            *(uint32_t*)(g_THl + rb1 + o) = pkh2(r0, r1);
        }
    } else if (z == 1) {   // phi -> fp16 single
        const int nrow = n0 + 16 * w + g;
        const size_t rb0 = ((size_t)b * NPOS + nrow) * CI;
        const size_t rb1 = rb0 + (size_t)8 * CI;
        #pragma unroll
        for (int j = 0; j < 16; j++) {
            int o = 8 * j + 2 * tc;
            float b0 = bias[o], b1 = bias[o + 1];
            *(uint32_t*)(g_PH + rb0 + o) = pkh2(acc[j][0] + b0, acc[j][1] + b1);
            *(uint32_t*)(g_PH + rb1 + o) = pkh2(acc[j][2] + b0, acc[j][3] + b1);
        }
    } else {               // g -> fp16 single [b][c][n]
        const int o = 16 * w + g;
        const float b0 = bias[o], b8 = bias[o + 8];
        #pragma unroll
        for (int j = 0; j < 16; j++) {
            int n = 16 * (j >> 1) + 8 * (j & 1) + 2 * tc;
            size_t a0 = ((size_t)b * CI + o) * NPOS + n0 + n;
            size_t a8 = a0 + (size_t)8 * NPOS;
            *(uint32_t*)(g_G + a0) = pkh2(acc[j][0] + b0, acc[j][1] + b0);
            *(uint32_t*)(g_G + a8) = pkh2(acc[j][2] + b8, acc[j][3] + b8);
        }
    }
}

// =================================================================
// K2: attention — 128 thr / 64 q / occ 2. QK fp16 2-term (theta exact
// split, phi single fp16), PV fp16 flash, W-conv fp16 full-W.
// =================================================================
#define SQ   272
#define SPG  144
#define SM_K0   0            // K single fp16, 17408/buf
#define SM_K1   17408
#define SM_G0   34816        // G buf (18432/buf)
#define SM_G1   53248
#define SM_QSTG 34816        // Q staging aliases G region (hi @0, lo @+17408)
#define SMEM_BYTES 71680
#define SM_WB   0            // epilogue: full 256-row W tile (69632 B)

__global__ __launch_bounds__(128, 2) void attn_mma_kernel(const float* __restrict__ W_b)
{
    extern __shared__ __align__(16) char smem[];
    const uint32_t sb = s2u(smem);
    const int t = threadIdx.x, w = t >> 5, L = t & 31;
    const int b = blockIdx.y;
    const int q0 = blockIdx.x * 64;
    const int g  = L >> 2, tc = L & 3;

    const __half* qh  = g_THh + ((size_t)b * NPOS + q0) * CI;
    const __half* ql  = g_THl + ((size_t)b * NPOS + q0) * CI;
    const __half* khb = g_PH + (size_t)b * NPOS * CI;
    const __half* ghb = g_G + (size_t)b * CI * NPOS;

    // prologue group 1: Q -> staging (G region), K(0) -> K0
    for (int i = t; i < 1024; i += 128) {           // Q: 64 rows x 16 chunks x2 splits
        int r = i >> 4, c16 = i & 15;
        uint32_t doff = (uint32_t)(r * SQ + c16 * 16);
        cpa16(sb + SM_QSTG + doff, qh + (size_t)r * CI + c16 * 8);
        cpa16(sb + SM_QSTG + 17408 + doff, ql + (size_t)r * CI + c16 * 8);
    }
    for (int i = t; i < 1024; i += 128) {           // K(0): single split
        int r = i >> 4, c16 = i & 15;
        cpa16(sb + SM_K0 + (uint32_t)(r * SQ + c16 * 16), khb + (size_t)r * CI + c16 * 8);
    }
    CP_COMMIT();

    const int lr = ((L >> 3) & 1) * 8 + (L & 7);
    const int lk = (L >> 4) * 16;
    const int bn = (L >> 4) * 8 + (L & 7);
    const int bk = ((L >> 3) & 1) * 16;

    const uint32_t kOff = (uint32_t)(bn * SQ + bk);
    const uint32_t gOff = (uint32_t)(bn * SPG + bk);

    // hoist Q fragments (fp16 hi/lo), then release staging for G
    CP_WAIT0();
    __syncthreads();
    uint32_t qfh[8][4], qfl[8][4];
    {
        const uint32_t aQ = sb + SM_QSTG + (uint32_t)((16 * w + lr) * SQ + lk);
        #pragma unroll
        for (int kk = 0; kk < 8; kk++) {
            ldsm4(qfh[kk], aQ + kk * 32);
            ldsm4(qfl[kk], aQ + 17408 + kk * 32);
        }
    }
    __syncthreads();   // all warps done reading staging

    // prologue group 2: G(0) -> G0
    for (int i = t; i < 1024; i += 128) {
        int r = i >> 3, c8 = i & 7;
        cpa16(sb + SM_G0 + (uint32_t)(r * SPG + c8 * 16), ghb + (size_t)r * NPOS + c8 * 8);
    }
    CP_COMMIT();

    float yacc[16][4];
    #pragma unroll
    for (int n = 0; n < 16; n++)
        #pragma unroll
        for (int j = 0; j < 4; j++) yacc[n][j] = 0.f;
    float ls0 = 0.f, ls1 = 0.f;
    float m0 = -INFINITY, m1 = -INFINITY;

    #pragma unroll 1
    for (int mt = 0; mt < NPOS / 64; mt++) {
        CP_WAIT0();
        __syncthreads();   // K(mt), G(mt) ready; prev-buffer readers done

        if (mt < 63) {
            const int m1i = mt * 64 + 64;
            const uint32_t kdst = sb + (((mt + 1) & 1) ? SM_K1 : SM_K0);
            const uint32_t gdst = sb + (((mt + 1) & 1) ? SM_G1 : SM_G0);
            for (int i = t; i < 1024; i += 128) {
                int r = i >> 4, c16 = i & 15;
                cpa16(kdst + (uint32_t)(r * SQ + c16 * 16),
                      khb + (size_t)(m1i + r) * CI + c16 * 8);
            }
            for (int i = t; i < 1024; i += 128) {
                int r = i >> 3, c8 = i & 7;
                cpa16(gdst + (uint32_t)(r * SPG + c8 * 16),
                      ghb + (size_t)r * NPOS + m1i + c8 * 8);
            }
            CP_COMMIT();
        }

        // ---- QK: fp16 2-term (qfh + qfl vs single K) ----
        const uint32_t bK = sb + ((mt & 1) ? SM_K1 : SM_K0) + kOff;
        float acc[8][4];
        #pragma unroll
        for (int n = 0; n < 8; n++)
            #pragma unroll
            for (int j = 0; j < 4; j++) acc[n][j] = 0.f;
        #pragma unroll
        for (int kk = 0; kk < 8; kk++) {
            #pragma unroll
            for (int np = 0; np < 4; np++) {
                uint32_t bh[4];
                ldsm4(bh, bK + np * (16 * SQ) + kk * 32);
                mma16816h(acc[2 * np],     qfh[kk], bh[0], bh[1]);
                mma16816h(acc[2 * np + 1], qfh[kk], bh[2], bh[3]);
                mma16816h(acc[2 * np],     qfl[kk], bh[0], bh[1]);
                mma16816h(acc[2 * np + 1], qfl[kk], bh[2], bh[3]);
            }
        }

        // ---- flash online-max softmax (skip-rescale vote) ----
        float tm0 = -INFINITY, tm1 = -INFINITY;
        #pragma unroll
        for (int n = 0; n < 8; n++) {
            tm0 = fmaxf(tm0, fmaxf(acc[n][0], acc[n][1]));
            tm1 = fmaxf(tm1, fmaxf(acc[n][2], acc[n][3]));
        }
        tm0 = fmaxf(tm0, __shfl_xor_sync(0xffffffffu, tm0, 1));
        tm0 = fmaxf(tm0, __shfl_xor_sync(0xffffffffu, tm0, 2));
        tm1 = fmaxf(tm1, __shfl_xor_sync(0xffffffffu, tm1, 1));
        tm1 = fmaxf(tm1, __shfl_xor_sync(0xffffffffu, tm1, 2));
        bool noup = (tm0 <= m0) && (tm1 <= m1);
        if (!__all_sync(0xffffffffu, noup)) {
            float mn0 = fmaxf(m0, tm0), mn1 = fmaxf(m1, tm1);
            float al0 = __expf(m0 - mn0), al1 = __expf(m1 - mn1);
            m0 = mn0; m1 = mn1;
            ls0 *= al0; ls1 *= al1;
            #pragma unroll
            for (int n = 0; n < 16; n++) {
                yacc[n][0] *= al0; yacc[n][1] *= al0;
                yacc[n][2] *= al1; yacc[n][3] *= al1;
            }
        }

        uint32_t pf[4][4];
        #pragma unroll
        for (int n = 0; n < 8; n++) {
            float p0 = __expf(acc[n][0] - m0);
            float p1 = __expf(acc[n][1] - m0);
            float p2 = __expf(acc[n][2] - m1);
            float p3 = __expf(acc[n][3] - m1);
            ls0 += p0 + p1;
            ls1 += p2 + p3;
            int kk = n >> 1, e = (n & 1) * 2;
            pf[kk][e]     = pkh2(p0, p1);
            pf[kk][e + 1] = pkh2(p2, p3);
        }

        // ---- PV (fp16 single term) ----
        const uint32_t bG = sb + ((mt & 1) ? SM_G1 : SM_G0) + gOff;
        #pragma unroll
        for (int kk = 0; kk < 4; kk++) {
            #pragma unroll
            for (int np = 0; np < 8; np++) {
                uint32_t bh[4];
                ldsm4(bh, bG + np * (16 * SPG) + kk * 32);
                mma16816h(yacc[2 * np],     pf[kk], bh[0], bh[1]);
                mma16816h(yacc[2 * np + 1], pf[kk], bh[2], bh[3]);
            }
        }
    }

    // ---- finalize row sums ----
    ls0 += __shfl_xor_sync(0xffffffffu, ls0, 1);
    ls0 += __shfl_xor_sync(0xffffffffu, ls0, 2);
    ls1 += __shfl_xor_sync(0xffffffffu, ls1, 1);
    ls1 += __shfl_xor_sync(0xffffffffu, ls1, 2);

    uint32_t yf[8][4];
    {
        float rv0 = 1.f / ls0, rv1 = 1.f / ls1;
        #pragma unroll
        for (int n = 0; n < 16; n++) {
            int kk = n >> 1, e = (n & 1) * 2;
            yf[kk][e]     = pkh2(yacc[n][0] * rv0, yacc[n][1] * rv0);
            yf[kk][e + 1] = pkh2(yacc[n][2] * rv1, yacc[n][3] * rv1);
        }
    }

    // ---- WY = W_w @ Y + W_b : stage FULL 256-row W once ----
    __syncthreads();
    for (int i = t; i < 4096; i += 128) {
        int r = i >> 4, c16 = i & 15;
        *(uint4*)(smem + SM_WB + (uint32_t)(r * SQ + c16 * 16)) =
            *(const uint4*)(g_Whalf + (size_t)r * CI + c16 * 8);
    }
    __syncthreads();

    const uint32_t bW = sb + SM_WB + (uint32_t)(bn * SQ + bk);
    float* WYb = g_WY + (size_t)b * CIN * NPOS + q0;

    #pragma unroll 1
    for (int h = 0; h < 2; h++) {
        const uint32_t bWh_ = bW + (uint32_t)(h * 128 * SQ);
        float wacc[16][4];
        #pragma unroll
        for (int n = 0; n < 16; n++)
            #pragma unroll
            for (int j = 0; j < 4; j++) wacc[n][j] = 0.f;

        #pragma unroll
        for (int kk = 0; kk < 8; kk++) {
            #pragma unroll
            for (int np = 0; np < 8; np++) {
                uint32_t bh[4];
                ldsm4(bh, bWh_ + np * (16 * SQ) + kk * 32);
                mma16816h(wacc[2 * np],     yf[kk], bh[0], bh[1]);
                mma16816h(wacc[2 * np + 1], yf[kk], bh[2], bh[3]);
            }
        }

        #pragma unroll
        for (int n = 0; n < 16; n++) {
            int o = h * 128 + 8 * n + 2 * tc;
            float b0 = __ldg(&W_b[o]);
            float b1 = __ldg(&W_b[o + 1]);
            int r0 = 16 * w + g;
            WYb[(size_t)o * NPOS + r0]           = wacc[n][0] + b0;
            WYb[(size_t)(o + 1) * NPOS + r0]     = wacc[n][1] + b1;
            WYb[(size_t)o * NPOS + r0 + 8]       = wacc[n][2] + b0;
            WYb[(size_t)(o + 1) * NPOS + r0 + 8] = wacc[n][3] + b1;
        }
    }
}

// =================================================================
// K3: BN statistics — partial pass + finalize
// =================================================================
__global__ __launch_bounds__(256) void stats_part_kernel()
{
    const int c = blockIdx.x;
    const int s = blockIdx.y;
    const int t = threadIdx.x;
    float sm = 0.f, ss = 0.f;
    for (int b = 2 * s; b < 2 * s + 2; b++) {
        const float* p = g_WY + ((size_t)b * CIN + c) * NPOS;
        for (int i = t; i < NPOS / 4; i += 256) {
            float4 v = *(const float4*)&p[4 * i];
            sm += v.x + v.y + v.z + v.w;
            ss += v.x * v.x + v.y * v.y + v.z * v.z + v.w * v.w;
        }
    }
    __shared__ float rs[256], rss[256];
    rs[t] = sm; rss[t] = ss;
    __syncthreads();
    for (int o = 128; o > 0; o >>= 1) {
        if (t < o) { rs[t] += rs[t + o]; rss[t] += rss[t + o]; }
        __syncthreads();
    }
    if (t == 0) {
        g_ps[s * CIN + c]  = rs[0];
        g_pss[s * CIN + c] = rss[0];
    }
}

__global__ __launch_bounds__(256) void stats_fin_kernel()
{
    const int c = threadIdx.x;
    float sm = g_ps[c] + g_ps[CIN + c] + g_ps[2 * CIN + c] + g_ps[3 * CIN + c];
    float ss = g_pss[c] + g_pss[CIN + c] + g_pss[2 * CIN + c] + g_pss[3 * CIN + c];
    const float inv = 1.f / (float)(BATCH * NPOS);
    float mean = sm * inv;
    float var  = ss * inv - mean * mean;
    g_mean[c] = mean;
    g_rstd[c] = rsqrtf(var + 1e-5f);
}

// =================================================================
// K4: z = (wy - mean)*rstd*gamma + beta + x
// =================================================================
__global__ __launch_bounds__(256) void final_kernel(
    const float* __restrict__ x,
    const float* __restrict__ gamma, const float* __restrict__ beta,
    float* __restrict__ z)
{
    size_t i4 = (size_t)blockIdx.x * 256 + threadIdx.x;
    size_t i  = i4 * 4;
    int c = (int)((i >> 12) & 255);
    float m = g_mean[c], r = g_rstd[c], ga = gamma[c], be = beta[c];
    float4 wy = *(const float4*)&g_WY[i];
    float4 xv = *(const float4*)&x[i];
    float4 o;
    o.x = (wy.x - m) * r * ga + be + xv.x;
    o.y = (wy.y - m) * r * ga + be + xv.y;
    o.z = (wy.z - m) * r * ga + be + xv.z;
    o.w = (wy.w - m) * r * ga + be + xv.w;
    *(float4*)&z[i] = o;
}

// =================================================================
extern "C" void kernel_launch(void* const* d_in, const int* in_sizes, int n_in,
                              void* d_out, int out_size)
{
    const float* x       = (const float*)d_in[0];
    const float* g_w     = (const float*)d_in[1];
    const float* g_b     = (const float*)d_in[2];
    const float* theta_w = (const float*)d_in[3];
    const float* theta_b = (const float*)d_in[4];
    const float* phi_w   = (const float*)d_in[5];
    const float* phi_b   = (const float*)d_in[6];
    const float* W_w     = (const float*)d_in[7];
    const float* W_b     = (const float*)d_in[8];
    const float* bn_g    = (const float*)d_in[9];
    const float* bn_b    = (const float*)d_in[10];
    float* z = (float*)d_out;

    cudaFuncSetAttribute(proj_all_kernel, cudaFuncAttributeMaxDynamicSharedMemorySize, PA_SMEM);
    cudaFuncSetAttribute(attn_mma_kernel, cudaFuncAttributeMaxDynamicSharedMemorySize, SMEM_BYTES);

    split_wts_kernel<<<512, 256>>>(theta_w, phi_w, g_w, W_w);
    proj_all_kernel<<<dim3(32, 8, 3), 256, PA_SMEM>>>(x, theta_b, phi_b, g_b);
    attn_mma_kernel<<<dim3(64, 8), 128, SMEM_BYTES>>>(W_b);
    stats_part_kernel<<<dim3(256, 4), 256>>>();
    stats_fin_kernel<<<1, 256>>>();
    final_kernel<<<8192, 256>>>(x, bn_g, bn_b, z);
}